// round 1
// baseline (speedup 1.0000x reference)
#include <cuda_runtime.h>
#include <cuda_bf16.h>
#include <cstdint>
#include <cstddef>

// Problem constants
#define RB 64      // batch
#define RT 512     // time steps
#define RI 512     // input dim
#define RH 1024    // hidden dim
#define RO 512     // output dim

// ---------------------------------------------------------------------------
// Scratch (device globals; no allocation allowed)
// ---------------------------------------------------------------------------
__device__ float g_xp[(size_t)RB * RT * RH];   // 128 MB: x_proj, then hidden states (in place)
__device__ float g_h[2 * RH * RB];             // ping-pong hidden, layout [buf][j][b] (column-major)
__device__ unsigned g_bar[4];                  // per-batch-group barrier counters

// ---------------------------------------------------------------------------
// Packed fp32x2 helpers (Blackwell dual-FP32 path; ptxas won't auto-fuse)
// ---------------------------------------------------------------------------
__device__ __forceinline__ unsigned long long pk2(float lo, float hi) {
    unsigned long long r;
    asm("mov.b64 %0,{%1,%2};" : "=l"(r) : "f"(lo), "f"(hi));
    return r;
}
__device__ __forceinline__ unsigned long long f2fma(unsigned long long a,
                                                    unsigned long long b,
                                                    unsigned long long c) {
    unsigned long long d;
    asm("fma.rn.f32x2 %0,%1,%2,%3;" : "=l"(d) : "l"(a), "l"(b), "l"(c));
    return d;
}
__device__ __forceinline__ void upk2(unsigned long long v, float& lo, float& hi) {
    asm("mov.b64 {%0,%1},%2;" : "=f"(lo), "=f"(hi) : "l"(v));
}

// ---------------------------------------------------------------------------
// Init: zero barrier counters, copy initial_hidden [b][j] -> g_h buf0 [j][b]
// ---------------------------------------------------------------------------
__global__ void rnn_init(const float* __restrict__ h0) {
    int bid = blockIdx.x;
    if (bid < 256) {
        int idx = bid * 256 + threadIdx.x;      // 0..65535
        int b = idx >> 10;
        int j = idx & 1023;
        g_h[j * RB + b] = h0[idx];
    } else {
        if (threadIdx.x < 4) g_bar[threadIdx.x] = 0;
    }
}

// ---------------------------------------------------------------------------
// SGEMM with bias:  C[M,N] = A[M,K] @ B[K,N] + bias[N]   (fp32, f32x2 FMAs)
// 128x128 tile, BK=8, 256 threads, 8x8 per thread.
// Requires M%128==0, N%128==0, K%8==0 (all true here).
// ---------------------------------------------------------------------------
__global__ void __launch_bounds__(256) sgemm_bias(
    int M, int N, int K,
    const float* __restrict__ A, const float* __restrict__ B,
    const float* __restrict__ bias, float* __restrict__ C)
{
    __shared__ float As[8][128];   // transposed A tile
    __shared__ float Bs[8][128];

    const int tid  = threadIdx.x;
    const int brow = blockIdx.y, bcol = blockIdx.x;
    const int trow = tid >> 4, tcol = tid & 15;
    const int aRow = tid >> 1, aCol = (tid & 1) << 2;
    const int bRow = tid >> 5, bCol = (tid & 31) << 2;

    const float* Ag = A + (size_t)(brow * 128 + aRow) * K + aCol;
    const float* Bg = B + (size_t)bRow * N + bcol * 128 + bCol;

    unsigned long long acc[8][4];
#pragma unroll
    for (int i = 0; i < 8; i++)
#pragma unroll
        for (int j = 0; j < 4; j++) acc[i][j] = 0ULL;

    for (int k0 = 0; k0 < K; k0 += 8) {
        float4 av = *(const float4*)(Ag + k0);
        float4 bv = *(const float4*)(Bg + (size_t)k0 * N);
        As[aCol + 0][aRow] = av.x;
        As[aCol + 1][aRow] = av.y;
        As[aCol + 2][aRow] = av.z;
        As[aCol + 3][aRow] = av.w;
        *(float4*)&Bs[bRow][bCol] = bv;
        __syncthreads();
#pragma unroll
        for (int kk = 0; kk < 8; kk++) {
            float4 a0 = *(const float4*)&As[kk][trow * 8];
            float4 a1 = *(const float4*)&As[kk][trow * 8 + 4];
            ulonglong2 b0 = *(const ulonglong2*)&Bs[kk][tcol * 8];
            ulonglong2 b1 = *(const ulonglong2*)&Bs[kk][tcol * 8 + 4];
            unsigned long long ap[8];
            ap[0] = pk2(a0.x, a0.x); ap[1] = pk2(a0.y, a0.y);
            ap[2] = pk2(a0.z, a0.z); ap[3] = pk2(a0.w, a0.w);
            ap[4] = pk2(a1.x, a1.x); ap[5] = pk2(a1.y, a1.y);
            ap[6] = pk2(a1.z, a1.z); ap[7] = pk2(a1.w, a1.w);
#pragma unroll
            for (int i = 0; i < 8; i++) {
                acc[i][0] = f2fma(ap[i], b0.x, acc[i][0]);
                acc[i][1] = f2fma(ap[i], b0.y, acc[i][1]);
                acc[i][2] = f2fma(ap[i], b1.x, acc[i][2]);
                acc[i][3] = f2fma(ap[i], b1.y, acc[i][3]);
            }
        }
        __syncthreads();
    }

    // Epilogue: add bias, store
    const int cb = bcol * 128 + tcol * 8;
    float bs[8];
#pragma unroll
    for (int j = 0; j < 8; j++) bs[j] = bias[cb + j];
#pragma unroll
    for (int i = 0; i < 8; i++) {
        int r = brow * 128 + trow * 8 + i;
        float c[8];
#pragma unroll
        for (int jp = 0; jp < 4; jp++) upk2(acc[i][jp], c[jp * 2], c[jp * 2 + 1]);
        float4 v0 = make_float4(c[0] + bs[0], c[1] + bs[1], c[2] + bs[2], c[3] + bs[3]);
        float4 v1 = make_float4(c[4] + bs[4], c[5] + bs[5], c[6] + bs[6], c[7] + bs[7]);
        *(float4*)&C[(size_t)r * N + cb]     = v0;
        *(float4*)&C[(size_t)r * N + cb + 4] = v1;
    }
}

// ---------------------------------------------------------------------------
// Persistent recurrent scan.
// Grid = 128 CTAs (1/SM, all co-resident): 4 batch groups (16 batches each)
// x 32 col groups (32 cols each). W_hh slice cached in smem for all 512 steps.
// Per step: load h slice (cg, bypass stale L1) -> tiny GEMM with f32x2 ->
// tanh(x_proj + .) -> store hidden state (for output GEMM) + next-h (col-major)
// -> per-group counter barrier.
// ---------------------------------------------------------------------------
__global__ void __launch_bounds__(256) rnn_scan_kernel(
    const float* __restrict__ W_hh, float* __restrict__ out)
{
    extern __shared__ float sm[];
    float* Wsm = sm;               // [1024][32]  = 128 KB
    float* Hsm = sm + 1024 * 32;   // [1024][16]  =  64 KB
    float* Red = Hsm;              // reduction buffer aliases Hsm (guarded by syncs)

    const int cta = blockIdx.x;
    const int g   = cta >> 5;          // batch group 0..3
    const int cg  = cta & 31;          // col group 0..31
    const int gb0 = g << 4;            // first batch of group
    const int gj0 = cg << 5;           // first col of group
    const int tid = threadIdx.x;

    // Load W_hh[:, gj0:gj0+32] into smem once.
    for (int idx = tid; idx < 1024 * 8; idx += 256) {
        int k = idx >> 3, j4 = (idx & 7) << 2;
        *(float4*)&Wsm[k * 32 + j4] =
            *(const float4*)&W_hh[(size_t)k * RH + gj0 + j4];
    }

    // Compute decomposition: 32 output positions x 8 k-slices
    const int p   = tid & 31;          // output position
    const int s   = tid >> 5;          // k slice
    const int bq4 = (p >> 3) << 2;     // batch quad base (0,4,8,12)
    const int jq4 = (p & 7) << 2;      // col quad base (0..28)
    const int k0  = s << 7;            // k slice start

    for (int t = 0; t < RT; ++t) {
        const float* hsrc = g_h + (t & 1) * (RH * RB);
        float*       hdst = g_h + ((t + 1) & 1) * (RH * RB);

        // Load h[gb0:gb0+16, :] (stored col-major [j][b]) into Hsm[k][b].
        for (int idx = tid; idx < 1024 * 4; idx += 256) {
            int k = idx >> 2, b4 = (idx & 3) << 2;
            float4 v = __ldcg((const float4*)(hsrc + (size_t)k * RB + gb0 + b4));
            *(float4*)&Hsm[k * 16 + b4] = v;
        }
        __syncthreads();   // Hsm ready (also covers Wsm at t==0)

        unsigned long long acc[4][2];
#pragma unroll
        for (int i = 0; i < 4; i++) { acc[i][0] = 0ULL; acc[i][1] = 0ULL; }

#pragma unroll 4
        for (int k = k0; k < k0 + 128; ++k) {
            float4 hv = *(const float4*)&Hsm[k * 16 + bq4];
            ulonglong2 wv = *(const ulonglong2*)&Wsm[k * 32 + jq4];
            unsigned long long h0 = pk2(hv.x, hv.x), h1 = pk2(hv.y, hv.y);
            unsigned long long h2 = pk2(hv.z, hv.z), h3 = pk2(hv.w, hv.w);
            acc[0][0] = f2fma(h0, wv.x, acc[0][0]); acc[0][1] = f2fma(h0, wv.y, acc[0][1]);
            acc[1][0] = f2fma(h1, wv.x, acc[1][0]); acc[1][1] = f2fma(h1, wv.y, acc[1][1]);
            acc[2][0] = f2fma(h2, wv.x, acc[2][0]); acc[2][1] = f2fma(h2, wv.y, acc[2][1]);
            acc[3][0] = f2fma(h3, wv.x, acc[3][0]); acc[3][1] = f2fma(h3, wv.y, acc[3][1]);
        }
        __syncthreads();   // done reading Hsm; Red may now alias it

        // Write partials: Red[(s*32+p)*17 + i], i = bi*4+ji  (17 = bank-conflict pad)
        {
            float c[16];
#pragma unroll
            for (int bi = 0; bi < 4; bi++) {
                upk2(acc[bi][0], c[bi * 4 + 0], c[bi * 4 + 1]);
                upk2(acc[bi][1], c[bi * 4 + 2], c[bi * 4 + 3]);
            }
            float* rp = &Red[(s * 32 + p) * 17];
#pragma unroll
            for (int i = 0; i < 16; i++) rp[i] = c[i];
        }
        __syncthreads();

        // Finalize: each thread reduces 2 outputs, applies tanh, stores.
#pragma unroll
        for (int u = 0; u < 2; u++) {
            int o  = tid * 2 + u;          // 0..511
            int pp = o >> 4, ii = o & 15;
            float v = 0.f;
#pragma unroll
            for (int ss = 0; ss < 8; ++ss) v += Red[(ss * 32 + pp) * 17 + ii];
            int bi = ii >> 2, ji = ii & 3;
            int b = ((pp >> 3) << 2) + bi;          // local batch 0..15
            int j = ((pp & 7) << 2) + ji;           // local col 0..31
            size_t xpi = ((size_t)(gb0 + b) * RT + t) * RH + gj0 + j;
            float hv = tanhf(v + g_xp[xpi]);
            g_xp[xpi] = hv;                          // hidden state for output GEMM
            hdst[(size_t)(gj0 + j) * RB + gb0 + b] = hv;  // next-step h (col-major)
            if (t == RT - 1)
                out[(size_t)RB * RT * RO + (size_t)(gb0 + b) * RH + gj0 + j] = hv;
        }

        // Per-group barrier (32 CTAs)
        __threadfence();
        __syncthreads();
        if (tid == 0) {
            atomicAdd(&g_bar[g], 1u);
            unsigned target = 32u * (unsigned)(t + 1);
            while (*(volatile unsigned*)&g_bar[g] < target) { }
            __threadfence();
        }
        __syncthreads();
    }
}

// ---------------------------------------------------------------------------
// Launch
// ---------------------------------------------------------------------------
extern "C" void kernel_launch(void* const* d_in, const int* in_sizes, int n_in,
                              void* d_out, int out_size)
{
    const float* inputs = (const float*)d_in[0];
    const float* h0     = (const float*)d_in[1];
    const float* W_xh   = (const float*)d_in[2];
    const float* W_hh   = (const float*)d_in[3];
    const float* W_hy   = (const float*)d_in[4];
    const float* b_h    = (const float*)d_in[5];
    const float* b_y    = (const float*)d_in[6];
    float* out = (float*)d_out;

    void* xp_ptr = nullptr;
    cudaGetSymbolAddress(&xp_ptr, g_xp);
    float* xp = (float*)xp_ptr;

    // Allow 192 KB dynamic smem for the scan kernel
    cudaFuncSetAttribute(rnn_scan_kernel,
                         cudaFuncAttributeMaxDynamicSharedMemorySize,
                         (1024 * 32 + 1024 * 16) * (int)sizeof(float));

    // 0) reset barriers, seed h0 (transposed)
    rnn_init<<<257, 256>>>(h0);

    // 1) x_proj = inputs @ W_xh + b_h   (M=32768, N=1024, K=512)
    sgemm_bias<<<dim3(RH / 128, (RB * RT) / 128), 256>>>(
        RB * RT, RH, RI, inputs, W_xh, b_h, xp);

    // 2) persistent recurrent scan (overwrites xp with hidden states,
    //    writes final_hidden into the tail of d_out)
    rnn_scan_kernel<<<128, 256, (1024 * 32 + 1024 * 16) * sizeof(float)>>>(W_hh, out);

    // 3) outputs = hidden_states @ W_hy + b_y   (M=32768, N=512, K=1024)
    sgemm_bias<<<dim3(RO / 128, (RB * RT) / 128), 256>>>(
        RB * RT, RO, RH, xp, W_hy, b_y, out);
}

// round 2
// speedup vs baseline: 1.1599x; 1.1599x over previous
#include <cuda_runtime.h>
#include <cuda_bf16.h>
#include <cstdint>
#include <cstddef>

// Problem constants
#define RB 64      // batch
#define RT 512     // time steps
#define RI 512     // input dim
#define RH 1024    // hidden dim
#define RO 512     // output dim

// ---------------------------------------------------------------------------
// Scratch (device globals; no allocation allowed)
// ---------------------------------------------------------------------------
__device__ float g_xp[(size_t)RB * RT * RH];   // 128 MB: x_proj, then hidden states (in place)
__device__ float g_h[2 * RH * RB];             // ping-pong hidden, layout [buf][j][b] (column-major)
__device__ unsigned g_bar[128];                // per-batch-group barrier counters (padded: slot g*32)

// ---------------------------------------------------------------------------
// Packed fp32x2 helpers (Blackwell dual-FP32 path; ptxas won't auto-fuse)
// ---------------------------------------------------------------------------
__device__ __forceinline__ unsigned long long pk2(float lo, float hi) {
    unsigned long long r;
    asm("mov.b64 %0,{%1,%2};" : "=l"(r) : "f"(lo), "f"(hi));
    return r;
}
__device__ __forceinline__ unsigned long long f2fma(unsigned long long a,
                                                    unsigned long long b,
                                                    unsigned long long c) {
    unsigned long long d;
    asm("fma.rn.f32x2 %0,%1,%2,%3;" : "=l"(d) : "l"(a), "l"(b), "l"(c));
    return d;
}
__device__ __forceinline__ void upk2(unsigned long long v, float& lo, float& hi) {
    asm("mov.b64 {%0,%1},%2;" : "=f"(lo), "=f"(hi) : "l"(v));
}

// ---------------------------------------------------------------------------
// Init: zero barrier counters, copy initial_hidden [b][j] -> g_h buf0 [j][b]
// ---------------------------------------------------------------------------
__global__ void rnn_init(const float* __restrict__ h0) {
    int bid = blockIdx.x;
    if (bid < 256) {
        int idx = bid * 256 + threadIdx.x;      // 0..65535
        int b = idx >> 10;
        int j = idx & 1023;
        g_h[j * RB + b] = h0[idx];
    } else {
        if (threadIdx.x < 128) g_bar[threadIdx.x] = 0;
    }
}

// ---------------------------------------------------------------------------
// SGEMM with bias:  C[M,N] = A[M,K] @ B[K,N] + bias[N]   (fp32, f32x2 FMAs)
// 128x128 tile, BK=8, 256 threads, 8x8 per thread.  (unchanged from R1 - known good)
// ---------------------------------------------------------------------------
__global__ void __launch_bounds__(256) sgemm_bias(
    int M, int N, int K,
    const float* __restrict__ A, const float* __restrict__ B,
    const float* __restrict__ bias, float* __restrict__ C)
{
    __shared__ float As[8][128];   // transposed A tile
    __shared__ float Bs[8][128];

    const int tid  = threadIdx.x;
    const int brow = blockIdx.y, bcol = blockIdx.x;
    const int trow = tid >> 4, tcol = tid & 15;
    const int aRow = tid >> 1, aCol = (tid & 1) << 2;
    const int bRow = tid >> 5, bCol = (tid & 31) << 2;

    const float* Ag = A + (size_t)(brow * 128 + aRow) * K + aCol;
    const float* Bg = B + (size_t)bRow * N + bcol * 128 + bCol;

    unsigned long long acc[8][4];
#pragma unroll
    for (int i = 0; i < 8; i++)
#pragma unroll
        for (int j = 0; j < 4; j++) acc[i][j] = 0ULL;

    for (int k0 = 0; k0 < K; k0 += 8) {
        float4 av = *(const float4*)(Ag + k0);
        float4 bv = *(const float4*)(Bg + (size_t)k0 * N);
        As[aCol + 0][aRow] = av.x;
        As[aCol + 1][aRow] = av.y;
        As[aCol + 2][aRow] = av.z;
        As[aCol + 3][aRow] = av.w;
        *(float4*)&Bs[bRow][bCol] = bv;
        __syncthreads();
#pragma unroll
        for (int kk = 0; kk < 8; kk++) {
            float4 a0 = *(const float4*)&As[kk][trow * 8];
            float4 a1 = *(const float4*)&As[kk][trow * 8 + 4];
            ulonglong2 b0 = *(const ulonglong2*)&Bs[kk][tcol * 8];
            ulonglong2 b1 = *(const ulonglong2*)&Bs[kk][tcol * 8 + 4];
            unsigned long long ap[8];
            ap[0] = pk2(a0.x, a0.x); ap[1] = pk2(a0.y, a0.y);
            ap[2] = pk2(a0.z, a0.z); ap[3] = pk2(a0.w, a0.w);
            ap[4] = pk2(a1.x, a1.x); ap[5] = pk2(a1.y, a1.y);
            ap[6] = pk2(a1.z, a1.z); ap[7] = pk2(a1.w, a1.w);
#pragma unroll
            for (int i = 0; i < 8; i++) {
                acc[i][0] = f2fma(ap[i], b0.x, acc[i][0]);
                acc[i][1] = f2fma(ap[i], b0.y, acc[i][1]);
                acc[i][2] = f2fma(ap[i], b1.x, acc[i][2]);
                acc[i][3] = f2fma(ap[i], b1.y, acc[i][3]);
            }
        }
        __syncthreads();
    }

    const int cb = bcol * 128 + tcol * 8;
    float bs[8];
#pragma unroll
    for (int j = 0; j < 8; j++) bs[j] = bias[cb + j];
#pragma unroll
    for (int i = 0; i < 8; i++) {
        int r = brow * 128 + trow * 8 + i;
        float c[8];
#pragma unroll
        for (int jp = 0; jp < 4; jp++) upk2(acc[i][jp], c[jp * 2], c[jp * 2 + 1]);
        float4 v0 = make_float4(c[0] + bs[0], c[1] + bs[1], c[2] + bs[2], c[3] + bs[3]);
        float4 v1 = make_float4(c[4] + bs[4], c[5] + bs[5], c[6] + bs[6], c[7] + bs[7]);
        *(float4*)&C[(size_t)r * N + cb]     = v0;
        *(float4*)&C[(size_t)r * N + cb + 4] = v1;
    }
}

// ---------------------------------------------------------------------------
// Persistent recurrent scan, v2.
// 128 CTAs (1/SM): 4 batch groups (16 batches) x 32 col groups (32 cols).
// 512 threads/CTA = 16 warps (4/SMSP) for latency hiding.
// Decomposition: warp s = k-slice (16 slices x 64 k), lane p: 4 batches x 4 cols.
// Inner loop: 2 LDS.128 + 4 movs + 8 f2fma per k (fma-pipe bound).
// ---------------------------------------------------------------------------
#define SCAN_THREADS 512
#define RED_STRIDE   544          // 16-slice reduction row stride (bank-safe)
#define SMEM_FLOATS  (1024*32 + 1024*16)   // Wsm + (Hsm|Red|Hout alias region)

__global__ void __launch_bounds__(SCAN_THREADS) rnn_scan_kernel(
    const float* __restrict__ W_hh, float* __restrict__ out)
{
    extern __shared__ float sm[];
    float* Wsm  = sm;                    // [1024][32] = 128 KB, resident all steps
    float* Hsm  = sm + 1024 * 32;        // [1024][16] =  64 KB (per-step h slice)
    float* Red  = Hsm;                   // 16*544 floats = 34 KB (aliases Hsm, sync-guarded)
    float* Hout = Hsm + 16 * RED_STRIDE; // [32 j][16 b] = 2 KB staging for coalesced h store

    const int cta = blockIdx.x;
    const int g   = cta >> 5;            // batch group 0..3
    const int cg  = cta & 31;            // col group 0..31
    const int gb0 = g << 4;              // first batch of group
    const int gj0 = cg << 5;             // first col of group
    const int tid = threadIdx.x;

    // Load W_hh[:, gj0:gj0+32] into smem once (1024x32 floats).
    for (int idx = tid; idx < 1024 * 8; idx += SCAN_THREADS) {
        int k = idx >> 3, j4 = (idx & 7) << 2;
        *(float4*)&Wsm[k * 32 + j4] =
            *(const float4*)&W_hh[(size_t)k * RH + gj0 + j4];
    }

    // Thread decomposition
    const int s    = tid >> 5;           // k-slice = warp id (0..15), 64 k each
    const int p    = tid & 31;           // lane
    const int bq4  = (p & 3) << 2;       // batch quad base {0,4,8,12}
    const int jq4  = (p >> 2) << 2;      // col quad base {0,4,...,28}
    const int k0   = s << 6;             // k slice start

    // Finalize-phase mapping: output o = tid
    const int fp = tid >> 4, fi = tid & 15;
    const int fb = ((fp & 3) << 2) + (fi >> 2);     // local batch 0..15
    const int fj = ((fp >> 2) << 2) + (fi & 3);     // local col 0..31

    unsigned* bar = &g_bar[g * 32];

    for (int t = 0; t < RT; ++t) {
        const float* hsrc = g_h + (t & 1) * (RH * RB);
        float*       hdst = g_h + ((t + 1) & 1) * (RH * RB);

        // Load h[gb0:gb0+16, :] ([j][b] col-major in global) into Hsm[k][b].
        for (int idx = tid; idx < 4096; idx += SCAN_THREADS) {
            int k = idx >> 2, b4 = (idx & 3) << 2;
            float4 v = __ldcg((const float4*)(hsrc + (size_t)k * RB + gb0 + b4));
            *(float4*)&Hsm[k * 16 + b4] = v;
        }
        // Prefetch x_proj for this thread's finalize output (independent of h).
        const size_t xpi = ((size_t)(gb0 + fb) * RT + t) * RH + gj0 + fj;
        const float xpv = g_xp[xpi];
        __syncthreads();   // Hsm ready (covers Wsm at t==0)

        unsigned long long acc[4][2];
#pragma unroll
        for (int i = 0; i < 4; i++) { acc[i][0] = 0ULL; acc[i][1] = 0ULL; }

        const float* hp = Hsm + k0 * 16 + bq4;
        const float* wp = Wsm + k0 * 32 + jq4;
#pragma unroll 8
        for (int kk = 0; kk < 64; ++kk) {
            float4 hv = *(const float4*)hp;
            ulonglong2 wv = *(const ulonglong2*)wp;
            unsigned long long h0 = pk2(hv.x, hv.x), h1 = pk2(hv.y, hv.y);
            unsigned long long h2 = pk2(hv.z, hv.z), h3 = pk2(hv.w, hv.w);
            acc[0][0] = f2fma(h0, wv.x, acc[0][0]); acc[0][1] = f2fma(h0, wv.y, acc[0][1]);
            acc[1][0] = f2fma(h1, wv.x, acc[1][0]); acc[1][1] = f2fma(h1, wv.y, acc[1][1]);
            acc[2][0] = f2fma(h2, wv.x, acc[2][0]); acc[2][1] = f2fma(h2, wv.y, acc[2][1]);
            acc[3][0] = f2fma(h3, wv.x, acc[3][0]); acc[3][1] = f2fma(h3, wv.y, acc[3][1]);
            hp += 16; wp += 32;
        }
        __syncthreads();   // all Hsm reads done; Red may alias

        // Write partials: Red[s*544 + p*17 + i], i = bi*4+ji (conflict-free).
        {
            float* rp = &Red[s * RED_STRIDE + p * 17];
#pragma unroll
            for (int bi = 0; bi < 4; bi++) {
                float c0, c1, c2, c3;
                upk2(acc[bi][0], c0, c1);
                upk2(acc[bi][1], c2, c3);
                rp[bi * 4 + 0] = c0; rp[bi * 4 + 1] = c1;
                rp[bi * 4 + 2] = c2; rp[bi * 4 + 3] = c3;
            }
        }
        __syncthreads();

        // Finalize: thread tid reduces its output, applies tanh, stores.
        {
            float v = 0.f;
            const float* rp = &Red[fp * 17 + fi];
#pragma unroll
            for (int ss = 0; ss < 16; ++ss) v += rp[ss * RED_STRIDE];
            float hv = tanhf(v + xpv);
            g_xp[xpi] = hv;                         // hidden state history (for output GEMM)
            Hout[fj * 16 + fb] = hv;                // stage for coalesced global store
            if (t == RT - 1)
                out[(size_t)RB * RT * RO + (size_t)(gb0 + fb) * RH + gj0 + fj] = hv;
        }
        __syncthreads();

        // Coalesced store of h slice to the ping-pong buffer.
        if (tid < 128) {
            int j = tid >> 2, b4 = (tid & 3) << 2;
            *(float4*)(hdst + (size_t)(gj0 + j) * RB + gb0 + b4) =
                *(const float4*)&Hout[j * 16 + b4];
        }

        // Per-group barrier (32 CTAs).
        __threadfence();
        __syncthreads();
        if (tid == 0) {
            atomicAdd(bar, 1u);
            unsigned target = 32u * (unsigned)(t + 1);
            while (*(volatile unsigned*)bar < target) __nanosleep(32);
            __threadfence();
        }
        __syncthreads();
    }
}

// ---------------------------------------------------------------------------
// Launch
// ---------------------------------------------------------------------------
extern "C" void kernel_launch(void* const* d_in, const int* in_sizes, int n_in,
                              void* d_out, int out_size)
{
    const float* inputs = (const float*)d_in[0];
    const float* h0     = (const float*)d_in[1];
    const float* W_xh   = (const float*)d_in[2];
    const float* W_hh   = (const float*)d_in[3];
    const float* W_hy   = (const float*)d_in[4];
    const float* b_h    = (const float*)d_in[5];
    const float* b_y    = (const float*)d_in[6];
    float* out = (float*)d_out;

    void* xp_ptr = nullptr;
    cudaGetSymbolAddress(&xp_ptr, g_xp);
    float* xp = (float*)xp_ptr;

    cudaFuncSetAttribute(rnn_scan_kernel,
                         cudaFuncAttributeMaxDynamicSharedMemorySize,
                         SMEM_FLOATS * (int)sizeof(float));

    // 0) reset barriers, seed h0 (transposed)
    rnn_init<<<257, 256>>>(h0);

    // 1) x_proj = inputs @ W_xh + b_h   (M=32768, N=1024, K=512)
    sgemm_bias<<<dim3(RH / 128, (RB * RT) / 128), 256>>>(
        RB * RT, RH, RI, inputs, W_xh, b_h, xp);

    // 2) persistent recurrent scan (overwrites xp with hidden states,
    //    writes final_hidden into the tail of d_out)
    rnn_scan_kernel<<<128, SCAN_THREADS, SMEM_FLOATS * sizeof(float)>>>(W_hh, out);

    // 3) outputs = hidden_states @ W_hy + b_y   (M=32768, N=512, K=1024)
    sgemm_bias<<<dim3(RO / 128, (RB * RT) / 128), 256>>>(
        RB * RT, RO, RH, xp, W_hy, b_y, out);
}

// round 3
// speedup vs baseline: 1.3785x; 1.1884x over previous
#include <cuda_runtime.h>
#include <cuda_bf16.h>
#include <cstdint>
#include <cstddef>

// Problem constants
#define RB 64      // batch
#define RT 512     // time steps
#define RI 512     // input dim
#define RH 1024    // hidden dim
#define RO 512     // output dim

// ---------------------------------------------------------------------------
// Scratch (device globals; no allocation allowed)
// ---------------------------------------------------------------------------
__device__ float g_xp[(size_t)RB * RT * RH];   // 128 MB: x_proj, then hidden states (in place)
__device__ float g_h[2 * RH * RB];             // ping-pong hidden, layout [buf][j][b]
__device__ unsigned g_bar[128];                // per-batch-group barrier counters (slot g*32)

// ---------------------------------------------------------------------------
// Packed fp32x2 helpers (scan stays full fp32)
// ---------------------------------------------------------------------------
__device__ __forceinline__ unsigned long long pk2(float lo, float hi) {
    unsigned long long r;
    asm("mov.b64 %0,{%1,%2};" : "=l"(r) : "f"(lo), "f"(hi));
    return r;
}
__device__ __forceinline__ unsigned long long f2fma(unsigned long long a,
                                                    unsigned long long b,
                                                    unsigned long long c) {
    unsigned long long d;
    asm("fma.rn.f32x2 %0,%1,%2,%3;" : "=l"(d) : "l"(a), "l"(b), "l"(c));
    return d;
}
__device__ __forceinline__ void upk2(unsigned long long v, float& lo, float& hi) {
    asm("mov.b64 {%0,%1},%2;" : "=f"(lo), "=f"(hi) : "l"(v));
}

// tf32 conversion (round-to-nearest; HW truncates if fed raw fp32)
__device__ __forceinline__ unsigned to_tf32(float f) {
    unsigned u;
    asm("cvt.rna.tf32.f32 %0,%1;" : "=r"(u) : "f"(f));
    return u;
}

// m16n8k8 tf32 MMA
__device__ __forceinline__ void mma_tf32(float* d,
                                         const unsigned* a, const unsigned* b,
                                         const float* c) {
    asm("mma.sync.aligned.m16n8k8.row.col.f32.tf32.tf32.f32 "
        "{%0,%1,%2,%3},{%4,%5,%6,%7},{%8,%9},{%10,%11,%12,%13};"
        : "=f"(d[0]), "=f"(d[1]), "=f"(d[2]), "=f"(d[3])
        : "r"(a[0]), "r"(a[1]), "r"(a[2]), "r"(a[3]),
          "r"(b[0]), "r"(b[1]),
          "f"(c[0]), "f"(c[1]), "f"(c[2]), "f"(c[3]));
}

// ---------------------------------------------------------------------------
// Init: zero barrier counters, copy initial_hidden [b][j] -> g_h buf0 [j][b]
// ---------------------------------------------------------------------------
__global__ void rnn_init(const float* __restrict__ h0) {
    int bid = blockIdx.x;
    if (bid < 256) {
        int idx = bid * 256 + threadIdx.x;      // 0..65535
        int b = idx >> 10;
        int j = idx & 1023;
        g_h[j * RB + b] = h0[idx];
    } else {
        if (threadIdx.x < 128) g_bar[threadIdx.x] = 0;
    }
}

// ---------------------------------------------------------------------------
// TF32 tensor-core GEMM with bias:  C[M,N] = A[M,K] @ B[K,N] + bias[N]
// 128x128x16 tile, 256 threads = 8 warps (4x2), warp tile 32x64.
// A smem [row][k] stride 20 (frag loads conflict-free);
// B smem [k][n]  stride 132 (frag loads <=2-way).
// Requires M%128==0, N%128==0, K%16==0.
// ---------------------------------------------------------------------------
#define ASTR 20
#define BSTR 132
__global__ void __launch_bounds__(256) gemm_tf32_bias(
    int M, int N, int K,
    const float* __restrict__ A, const float* __restrict__ B,
    const float* __restrict__ bias, float* __restrict__ C)
{
    __shared__ unsigned As[128 * ASTR];   // 10 KB
    __shared__ unsigned Bs[16 * BSTR];    // 8.25 KB

    const int tid  = threadIdx.x;
    const int lane = tid & 31, wid = tid >> 5;
    const int g  = lane >> 2, tg = lane & 3;
    const int wm = (wid & 3) << 5;          // warp M offset (0,32,64,96)
    const int wn = (wid >> 2) << 6;         // warp N offset (0,64)
    const int bx = blockIdx.x << 7, by = blockIdx.y << 7;

    // A tile loader: rows ar, ar+64; k quad akq
    const int ar  = tid >> 2, akq = (tid & 3) << 2;
    const float* Ag = A + (size_t)(by + ar) * K + akq;
    // B tile loader: rows bk, bk+8; col quad bc
    const int bk = tid >> 5, bc = (tid & 31) << 2;
    const float* Bg = B + (size_t)bk * N + bx + bc;

    float4 pa0 = *(const float4*)(Ag);
    float4 pa1 = *(const float4*)(Ag + (size_t)64 * K);
    float4 pb0 = *(const float4*)(Bg);
    float4 pb1 = *(const float4*)(Bg + (size_t)8 * N);

    float acc[2][8][4];
#pragma unroll
    for (int i = 0; i < 2; i++)
#pragma unroll
        for (int j = 0; j < 8; j++)
#pragma unroll
            for (int l = 0; l < 4; l++) acc[i][j][l] = 0.f;

    for (int k0 = 0; ; ) {
        // stage prefetched tile into smem (tf32-converted)
        {
            uint4 va0 = make_uint4(to_tf32(pa0.x), to_tf32(pa0.y), to_tf32(pa0.z), to_tf32(pa0.w));
            uint4 va1 = make_uint4(to_tf32(pa1.x), to_tf32(pa1.y), to_tf32(pa1.z), to_tf32(pa1.w));
            *(uint4*)&As[ar * ASTR + akq]        = va0;
            *(uint4*)&As[(ar + 64) * ASTR + akq] = va1;
            uint4 vb0 = make_uint4(to_tf32(pb0.x), to_tf32(pb0.y), to_tf32(pb0.z), to_tf32(pb0.w));
            uint4 vb1 = make_uint4(to_tf32(pb1.x), to_tf32(pb1.y), to_tf32(pb1.z), to_tf32(pb1.w));
            *(uint4*)&Bs[bk * BSTR + bc]       = vb0;
            *(uint4*)&Bs[(bk + 8) * BSTR + bc] = vb1;
        }
        __syncthreads();

        bool more = (k0 + 16) < K;
        if (more) {
            pa0 = *(const float4*)(Ag + k0 + 16);
            pa1 = *(const float4*)(Ag + (size_t)64 * K + k0 + 16);
            pb0 = *(const float4*)(Bg + (size_t)(k0 + 16) * N);
            pb1 = *(const float4*)(Bg + (size_t)(k0 + 24) * N);
        }

#pragma unroll
        for (int ks = 0; ks < 16; ks += 8) {
            unsigned af[2][4], bf[8][2];
#pragma unroll
            for (int mt = 0; mt < 2; mt++) {
                int r = wm + (mt << 4) + g;
                af[mt][0] = As[r * ASTR + ks + tg];
                af[mt][1] = As[(r + 8) * ASTR + ks + tg];
                af[mt][2] = As[r * ASTR + ks + tg + 4];
                af[mt][3] = As[(r + 8) * ASTR + ks + tg + 4];
            }
#pragma unroll
            for (int nt = 0; nt < 8; nt++) {
                int c = wn + (nt << 3) + g;
                bf[nt][0] = Bs[(ks + tg) * BSTR + c];
                bf[nt][1] = Bs[(ks + tg + 4) * BSTR + c];
            }
#pragma unroll
            for (int mt = 0; mt < 2; mt++)
#pragma unroll
                for (int nt = 0; nt < 8; nt++)
                    mma_tf32(acc[mt][nt], af[mt], bf[nt], acc[mt][nt]);
        }
        __syncthreads();

        k0 += 16;
        if (!more) break;
    }

    // Epilogue: add bias, store float2 pairs
#pragma unroll
    for (int mt = 0; mt < 2; mt++) {
        int r0 = by + wm + (mt << 4) + g;
#pragma unroll
        for (int nt = 0; nt < 8; nt++) {
            int col = bx + wn + (nt << 3) + (tg << 1);
            float b0v = bias[col], b1v = bias[col + 1];
            float2 v0 = make_float2(acc[mt][nt][0] + b0v, acc[mt][nt][1] + b1v);
            float2 v1 = make_float2(acc[mt][nt][2] + b0v, acc[mt][nt][3] + b1v);
            *(float2*)&C[(size_t)r0 * N + col]       = v0;
            *(float2*)&C[(size_t)(r0 + 8) * N + col] = v1;
        }
    }
}

// ---------------------------------------------------------------------------
// Persistent recurrent scan (unchanged from R2 — known-good 6.8us/step).
// ---------------------------------------------------------------------------
#define SCAN_THREADS 512
#define RED_STRIDE   544
#define SMEM_FLOATS  (1024*32 + 1024*16)

__global__ void __launch_bounds__(SCAN_THREADS) rnn_scan_kernel(
    const float* __restrict__ W_hh, float* __restrict__ out)
{
    extern __shared__ float sm[];
    float* Wsm  = sm;                    // [1024][32] = 128 KB
    float* Hsm  = sm + 1024 * 32;        // [1024][16] =  64 KB
    float* Red  = Hsm;                   // aliases Hsm (sync-guarded)
    float* Hout = Hsm + 16 * RED_STRIDE; // [32 j][16 b] staging

    const int cta = blockIdx.x;
    const int g   = cta >> 5;
    const int cg  = cta & 31;
    const int gb0 = g << 4;
    const int gj0 = cg << 5;
    const int tid = threadIdx.x;

    for (int idx = tid; idx < 1024 * 8; idx += SCAN_THREADS) {
        int k = idx >> 3, j4 = (idx & 7) << 2;
        *(float4*)&Wsm[k * 32 + j4] =
            *(const float4*)&W_hh[(size_t)k * RH + gj0 + j4];
    }

    const int s    = tid >> 5;
    const int p    = tid & 31;
    const int bq4  = (p & 3) << 2;
    const int jq4  = (p >> 2) << 2;
    const int k0   = s << 6;

    const int fp = tid >> 4, fi = tid & 15;
    const int fb = ((fp & 3) << 2) + (fi >> 2);
    const int fj = ((fp >> 2) << 2) + (fi & 3);

    unsigned* bar = &g_bar[g * 32];

    for (int t = 0; t < RT; ++t) {
        const float* hsrc = g_h + (t & 1) * (RH * RB);
        float*       hdst = g_h + ((t + 1) & 1) * (RH * RB);

        for (int idx = tid; idx < 4096; idx += SCAN_THREADS) {
            int k = idx >> 2, b4 = (idx & 3) << 2;
            float4 v = __ldcg((const float4*)(hsrc + (size_t)k * RB + gb0 + b4));
            *(float4*)&Hsm[k * 16 + b4] = v;
        }
        const size_t xpi = ((size_t)(gb0 + fb) * RT + t) * RH + gj0 + fj;
        const float xpv = g_xp[xpi];
        __syncthreads();

        unsigned long long acc[4][2];
#pragma unroll
        for (int i = 0; i < 4; i++) { acc[i][0] = 0ULL; acc[i][1] = 0ULL; }

        const float* hp = Hsm + k0 * 16 + bq4;
        const float* wp = Wsm + k0 * 32 + jq4;
#pragma unroll 8
        for (int kk = 0; kk < 64; ++kk) {
            float4 hv = *(const float4*)hp;
            ulonglong2 wv = *(const ulonglong2*)wp;
            unsigned long long h0 = pk2(hv.x, hv.x), h1 = pk2(hv.y, hv.y);
            unsigned long long h2 = pk2(hv.z, hv.z), h3 = pk2(hv.w, hv.w);
            acc[0][0] = f2fma(h0, wv.x, acc[0][0]); acc[0][1] = f2fma(h0, wv.y, acc[0][1]);
            acc[1][0] = f2fma(h1, wv.x, acc[1][0]); acc[1][1] = f2fma(h1, wv.y, acc[1][1]);
            acc[2][0] = f2fma(h2, wv.x, acc[2][0]); acc[2][1] = f2fma(h2, wv.y, acc[2][1]);
            acc[3][0] = f2fma(h3, wv.x, acc[3][0]); acc[3][1] = f2fma(h3, wv.y, acc[3][1]);
            hp += 16; wp += 32;
        }
        __syncthreads();

        {
            float* rp = &Red[s * RED_STRIDE + p * 17];
#pragma unroll
            for (int bi = 0; bi < 4; bi++) {
                float c0, c1, c2, c3;
                upk2(acc[bi][0], c0, c1);
                upk2(acc[bi][1], c2, c3);
                rp[bi * 4 + 0] = c0; rp[bi * 4 + 1] = c1;
                rp[bi * 4 + 2] = c2; rp[bi * 4 + 3] = c3;
            }
        }
        __syncthreads();

        {
            float v = 0.f;
            const float* rp = &Red[fp * 17 + fi];
#pragma unroll
            for (int ss = 0; ss < 16; ++ss) v += rp[ss * RED_STRIDE];
            float hv = tanhf(v + xpv);
            g_xp[xpi] = hv;
            Hout[fj * 16 + fb] = hv;
            if (t == RT - 1)
                out[(size_t)RB * RT * RO + (size_t)(gb0 + fb) * RH + gj0 + fj] = hv;
        }
        __syncthreads();

        if (tid < 128) {
            int j = tid >> 2, b4 = (tid & 3) << 2;
            *(float4*)(hdst + (size_t)(gj0 + j) * RB + gb0 + b4) =
                *(const float4*)&Hout[j * 16 + b4];
        }

        __threadfence();
        __syncthreads();
        if (tid == 0) {
            atomicAdd(bar, 1u);
            unsigned target = 32u * (unsigned)(t + 1);
            while (*(volatile unsigned*)bar < target) __nanosleep(32);
            __threadfence();
        }
        __syncthreads();
    }
}

// ---------------------------------------------------------------------------
// Launch
// ---------------------------------------------------------------------------
extern "C" void kernel_launch(void* const* d_in, const int* in_sizes, int n_in,
                              void* d_out, int out_size)
{
    const float* inputs = (const float*)d_in[0];
    const float* h0     = (const float*)d_in[1];
    const float* W_xh   = (const float*)d_in[2];
    const float* W_hh   = (const float*)d_in[3];
    const float* W_hy   = (const float*)d_in[4];
    const float* b_h    = (const float*)d_in[5];
    const float* b_y    = (const float*)d_in[6];
    float* out = (float*)d_out;

    void* xp_ptr = nullptr;
    cudaGetSymbolAddress(&xp_ptr, g_xp);
    float* xp = (float*)xp_ptr;

    cudaFuncSetAttribute(rnn_scan_kernel,
                         cudaFuncAttributeMaxDynamicSharedMemorySize,
                         SMEM_FLOATS * (int)sizeof(float));

    // 0) reset barriers, seed h0 (transposed)
    rnn_init<<<257, 256>>>(h0);

    // 1) x_proj = inputs @ W_xh + b_h   (M=32768, N=1024, K=512)  [tf32 TC]
    gemm_tf32_bias<<<dim3(RH / 128, (RB * RT) / 128), 256>>>(
        RB * RT, RH, RI, inputs, W_xh, b_h, xp);

    // 2) persistent recurrent scan (fp32)
    rnn_scan_kernel<<<128, SCAN_THREADS, SMEM_FLOATS * sizeof(float)>>>(W_hh, out);

    // 3) outputs = hidden_states @ W_hy + b_y   (M=32768, N=512, K=1024)  [tf32 TC]
    gemm_tf32_bias<<<dim3(RO / 128, (RB * RT) / 128), 256>>>(
        RB * RT, RO, RH, xp, W_hy, b_y, out);
}

// round 5
// speedup vs baseline: 1.5590x; 1.1309x over previous
#include <cuda_runtime.h>
#include <cuda_bf16.h>
#include <cstdint>
#include <cstddef>

// Problem constants
#define RB 64      // batch
#define RT 512     // time steps
#define RI 512     // input dim
#define RH 1024    // hidden dim
#define RO 512     // output dim
#define NBUF 4     // h ring-buffer depth (gives 3 steps of producer/consumer slack)

// ---------------------------------------------------------------------------
// Scratch (device globals; no allocation allowed)
// ---------------------------------------------------------------------------
__device__ float g_xp[(size_t)RB * RT * RH];   // 128 MB: x_proj, then hidden states (in place)
__device__ float g_h[NBUF * RH * RB];          // ring-buffered hidden, layout [buf][j][b]
__device__ unsigned g_wflag[128 * 32];         // per-CTA write flags  (steps written), 128B apart
__device__ unsigned g_rflag[128 * 32];         // per-CTA read flags   (steps read),    128B apart

// ---------------------------------------------------------------------------
// Packed fp32x2 helpers (scan stays full fp32)
// ---------------------------------------------------------------------------
__device__ __forceinline__ unsigned long long pk2(float lo, float hi) {
    unsigned long long r;
    asm("mov.b64 %0,{%1,%2};" : "=l"(r) : "f"(lo), "f"(hi));
    return r;
}
__device__ __forceinline__ unsigned long long f2fma(unsigned long long a,
                                                    unsigned long long b,
                                                    unsigned long long c) {
    unsigned long long d;
    asm("fma.rn.f32x2 %0,%1,%2,%3;" : "=l"(d) : "l"(a), "l"(b), "l"(c));
    return d;
}
__device__ __forceinline__ void upk2(unsigned long long v, float& lo, float& hi) {
    asm("mov.b64 {%0,%1},%2;" : "=f"(lo), "=f"(hi) : "l"(v));
}

// tf32 conversion (round-to-nearest)
__device__ __forceinline__ unsigned to_tf32(float f) {
    unsigned u;
    asm("cvt.rna.tf32.f32 %0,%1;" : "=r"(u) : "f"(f));
    return u;
}

// m16n8k8 tf32 MMA
__device__ __forceinline__ void mma_tf32(float* d,
                                         const unsigned* a, const unsigned* b,
                                         const float* c) {
    asm("mma.sync.aligned.m16n8k8.row.col.f32.tf32.tf32.f32 "
        "{%0,%1,%2,%3},{%4,%5,%6,%7},{%8,%9},{%10,%11,%12,%13};"
        : "=f"(d[0]), "=f"(d[1]), "=f"(d[2]), "=f"(d[3])
        : "r"(a[0]), "r"(a[1]), "r"(a[2]), "r"(a[3]),
          "r"(b[0]), "r"(b[1]),
          "f"(c[0]), "f"(c[1]), "f"(c[2]), "f"(c[3]));
}

// Release/acquire flag ops (gpu scope)
__device__ __forceinline__ void flag_release(unsigned* p, unsigned v) {
    asm volatile("st.release.gpu.global.u32 [%0],%1;" :: "l"(p), "r"(v) : "memory");
}
__device__ __forceinline__ unsigned flag_acquire(const unsigned* p) {
    unsigned v;
    asm volatile("ld.acquire.gpu.global.u32 %0,[%1];" : "=r"(v) : "l"(p) : "memory");
    return v;
}

// ---------------------------------------------------------------------------
// Init: zero flags, copy initial_hidden [b][j] -> g_h buf0 [j][b]
// ---------------------------------------------------------------------------
__global__ void rnn_init(const float* __restrict__ h0) {
    int bid = blockIdx.x;
    if (bid < 256) {
        int idx = bid * 256 + threadIdx.x;      // 0..65535
        int b = idx >> 10;
        int j = idx & 1023;
        g_h[j * RB + b] = h0[idx];
    } else {
        for (int i = threadIdx.x; i < 128 * 32; i += 256) {
            g_wflag[i] = 0;
            g_rflag[i] = 0;
        }
    }
}

// ---------------------------------------------------------------------------
// TF32 tensor-core GEMM with bias (unchanged — known good 309us each)
// ---------------------------------------------------------------------------
#define ASTR 20
#define BSTR 132
__global__ void __launch_bounds__(256) gemm_tf32_bias(
    int M, int N, int K,
    const float* __restrict__ A, const float* __restrict__ B,
    const float* __restrict__ bias, float* __restrict__ C)
{
    __shared__ unsigned As[128 * ASTR];
    __shared__ unsigned Bs[16 * BSTR];

    const int tid  = threadIdx.x;
    const int lane = tid & 31, wid = tid >> 5;
    const int g  = lane >> 2, tg = lane & 3;
    const int wm = (wid & 3) << 5;
    const int wn = (wid >> 2) << 6;
    const int bx = blockIdx.x << 7, by = blockIdx.y << 7;

    const int ar  = tid >> 2, akq = (tid & 3) << 2;
    const float* Ag = A + (size_t)(by + ar) * K + akq;
    const int bk = tid >> 5, bc = (tid & 31) << 2;
    const float* Bg = B + (size_t)bk * N + bx + bc;

    float4 pa0 = *(const float4*)(Ag);
    float4 pa1 = *(const float4*)(Ag + (size_t)64 * K);
    float4 pb0 = *(const float4*)(Bg);
    float4 pb1 = *(const float4*)(Bg + (size_t)8 * N);

    float acc[2][8][4];
#pragma unroll
    for (int i = 0; i < 2; i++)
#pragma unroll
        for (int j = 0; j < 8; j++)
#pragma unroll
            for (int l = 0; l < 4; l++) acc[i][j][l] = 0.f;

    for (int k0 = 0; ; ) {
        {
            uint4 va0 = make_uint4(to_tf32(pa0.x), to_tf32(pa0.y), to_tf32(pa0.z), to_tf32(pa0.w));
            uint4 va1 = make_uint4(to_tf32(pa1.x), to_tf32(pa1.y), to_tf32(pa1.z), to_tf32(pa1.w));
            *(uint4*)&As[ar * ASTR + akq]        = va0;
            *(uint4*)&As[(ar + 64) * ASTR + akq] = va1;
            uint4 vb0 = make_uint4(to_tf32(pb0.x), to_tf32(pb0.y), to_tf32(pb0.z), to_tf32(pb0.w));
            uint4 vb1 = make_uint4(to_tf32(pb1.x), to_tf32(pb1.y), to_tf32(pb1.z), to_tf32(pb1.w));
            *(uint4*)&Bs[bk * BSTR + bc]       = vb0;
            *(uint4*)&Bs[(bk + 8) * BSTR + bc] = vb1;
        }
        __syncthreads();

        bool more = (k0 + 16) < K;
        if (more) {
            pa0 = *(const float4*)(Ag + k0 + 16);
            pa1 = *(const float4*)(Ag + (size_t)64 * K + k0 + 16);
            pb0 = *(const float4*)(Bg + (size_t)(k0 + 16) * N);
            pb1 = *(const float4*)(Bg + (size_t)(k0 + 24) * N);
        }

#pragma unroll
        for (int ks = 0; ks < 16; ks += 8) {
            unsigned af[2][4], bf[8][2];
#pragma unroll
            for (int mt = 0; mt < 2; mt++) {
                int r = wm + (mt << 4) + g;
                af[mt][0] = As[r * ASTR + ks + tg];
                af[mt][1] = As[(r + 8) * ASTR + ks + tg];
                af[mt][2] = As[r * ASTR + ks + tg + 4];
                af[mt][3] = As[(r + 8) * ASTR + ks + tg + 4];
            }
#pragma unroll
            for (int nt = 0; nt < 8; nt++) {
                int c = wn + (nt << 3) + g;
                bf[nt][0] = Bs[(ks + tg) * BSTR + c];
                bf[nt][1] = Bs[(ks + tg + 4) * BSTR + c];
            }
#pragma unroll
            for (int mt = 0; mt < 2; mt++)
#pragma unroll
                for (int nt = 0; nt < 8; nt++)
                    mma_tf32(acc[mt][nt], af[mt], bf[nt], acc[mt][nt]);
        }
        __syncthreads();

        k0 += 16;
        if (!more) break;
    }

#pragma unroll
    for (int mt = 0; mt < 2; mt++) {
        int r0 = by + wm + (mt << 4) + g;
#pragma unroll
        for (int nt = 0; nt < 8; nt++) {
            int col = bx + wn + (nt << 3) + (tg << 1);
            float b0v = bias[col], b1v = bias[col + 1];
            float2 v0 = make_float2(acc[mt][nt][0] + b0v, acc[mt][nt][1] + b1v);
            float2 v1 = make_float2(acc[mt][nt][2] + b0v, acc[mt][nt][3] + b1v);
            *(float2*)&C[(size_t)r0 * N + col]       = v0;
            *(float2*)&C[(size_t)(r0 + 8) * N + col] = v1;
        }
    }
}

// ---------------------------------------------------------------------------
// Persistent recurrent scan, v4: fine-grained flags + 4-deep ring + read-acks.
// 128 CTAs (1/SM): 4 batch groups x 32 col groups. 512 threads = 16 warps.
//
// Sync protocol per step t (CTA = (g,cg)):
//   1. warp s waits wflag of producers (g,2s),(g,2s+1) >= t, then __syncwarp.
//   2. load own Hsm chunk from buf[t%4]; warp 15 early-loads 32 group rflags.
//   3. compute partial GEMM.
//   4. syncB; tid0 releases rflag=t+1 (this CTA done READING buf[t%4]).
//   5. write Red partials; warp 15 verifies all group rflags >= t-2
//      (=> buf[(t+1)%4], last read at step t-3, is free for rewrite).
//   6. syncC; finalize (tanh) stores h to buf[(t+1)%4] + g_xp.
//   7. syncD; tid0 releases wflag=t+1.
// Deadlock-free (rflag released before any poll); race-free (3-step slack,
// writes gated by consumer acks; producer visibility via release/acquire).
// ---------------------------------------------------------------------------
#define SCAN_THREADS 512
#define RED_STRIDE   544
#define SMEM_FLOATS  (1024*32 + 1024*16)

__global__ void __launch_bounds__(SCAN_THREADS) rnn_scan_kernel(
    const float* __restrict__ W_hh, float* __restrict__ out)
{
    extern __shared__ float sm[];
    float* Wsm  = sm;                    // [1024][32] = 128 KB, resident
    float* Hsm  = sm + 1024 * 32;        // [1024][16] =  64 KB (per-step h)
    float* Red  = Hsm;                   // 16*544 floats, aliases Hsm (sync-guarded)

    const int cta = blockIdx.x;
    const int g   = cta >> 5;            // batch group 0..3
    const int cg  = cta & 31;            // col group 0..31
    const int gb0 = g << 4;
    const int gj0 = cg << 5;
    const int tid = threadIdx.x;
    const int lane = tid & 31;

    // Load W_hh[:, gj0:gj0+32] into smem once.
    for (int idx = tid; idx < 1024 * 8; idx += SCAN_THREADS) {
        int k = idx >> 3, j4 = (idx & 7) << 2;
        *(float4*)&Wsm[k * 32 + j4] =
            *(const float4*)&W_hh[(size_t)k * RH + gj0 + j4];
    }

    const int s    = tid >> 5;           // warp id = k-slice (64 k each)
    const int p    = tid & 31;
    const int bq4  = (p & 3) << 2;
    const int jq4  = (p >> 2) << 2;
    const int k0   = s << 6;

    // finalize mapping
    const int fp = tid >> 4, fi = tid & 15;
    const int fb = ((fp & 3) << 2) + (fi >> 2);
    const int fj = ((fp >> 2) << 2) + (fi & 3);

    // warp's producer wflag (lane parity picks one of the 2 producers)
    const unsigned* prodflag = &g_wflag[((g << 5) + (s << 1) + (lane & 1)) * 32];
    // group rflag this lane monitors (warp 15 only)
    const unsigned* grflag = &g_rflag[((g << 5) + lane) * 32];
    unsigned* my_wflag = &g_wflag[cta * 32];
    unsigned* my_rflag = &g_rflag[cta * 32];

    __syncthreads();   // Wsm visible to all warps

    for (int t = 0; t < RT; ++t) {
        const float* hsrc = g_h + (size_t)(t & 3) * (RH * RB);
        float*       hdst = g_h + (size_t)((t + 1) & 3) * (RH * RB);

        // 1) wait for this warp's 2 producers to have written step t's h.
        if (t > 0) {
            const unsigned tgt = (unsigned)t;
            while (flag_acquire(prodflag) < tgt) __nanosleep(16);
            __syncwarp();   // both producers confirmed for ALL lanes
        }

        // 2) load own Hsm chunk: k in [k0, k0+64), 16 batches.
#pragma unroll
        for (int r = 0; r < 8; ++r) {
            int i = (r << 5) + lane;            // 0..255
            int k = k0 + (i >> 2), b4 = (i & 3) << 2;
            float4 v = __ldcg((const float4*)(hsrc + (size_t)k * RB + gb0 + b4));
            *(float4*)&Hsm[k * 16 + b4] = v;
        }
        // warp 15: early-load group read-acks (latency hidden under compute)
        unsigned rv = 0;
        if (s == 15) rv = flag_acquire(grflag);

        // x_proj prefetch for finalize (independent of h)
        const size_t xpi = ((size_t)(gb0 + fb) * RT + t) * RH + gj0 + fj;
        const float xpv = g_xp[xpi];

        // 3) compute partial GEMM over own chunk.
        unsigned long long acc[4][2];
#pragma unroll
        for (int i = 0; i < 4; i++) { acc[i][0] = 0ULL; acc[i][1] = 0ULL; }

        const float* hp = Hsm + k0 * 16 + bq4;
        const float* wp = Wsm + k0 * 32 + jq4;
#pragma unroll 8
        for (int kk = 0; kk < 64; ++kk) {
            float4 hv = *(const float4*)hp;
            ulonglong2 wv = *(const ulonglong2*)wp;
            unsigned long long h0 = pk2(hv.x, hv.x), h1 = pk2(hv.y, hv.y);
            unsigned long long h2 = pk2(hv.z, hv.z), h3 = pk2(hv.w, hv.w);
            acc[0][0] = f2fma(h0, wv.x, acc[0][0]); acc[0][1] = f2fma(h0, wv.y, acc[0][1]);
            acc[1][0] = f2fma(h1, wv.x, acc[1][0]); acc[1][1] = f2fma(h1, wv.y, acc[1][1]);
            acc[2][0] = f2fma(h2, wv.x, acc[2][0]); acc[2][1] = f2fma(h2, wv.y, acc[2][1]);
            acc[3][0] = f2fma(h3, wv.x, acc[3][0]); acc[3][1] = f2fma(h3, wv.y, acc[3][1]);
            hp += 16; wp += 32;
        }
        __syncthreads();   // B: all Hsm reads of buf[t%4] done

        // 4) publish read-ack (before any polling -> deadlock-free)
        if (tid == 0) flag_release(my_rflag, (unsigned)(t + 1));

        // 5a) write Red partials
        {
            float* rp = &Red[s * RED_STRIDE + p * 17];
#pragma unroll
            for (int bi = 0; bi < 4; bi++) {
                float c0, c1, c2, c3;
                upk2(acc[bi][0], c0, c1);
                upk2(acc[bi][1], c2, c3);
                rp[bi * 4 + 0] = c0; rp[bi * 4 + 1] = c1;
                rp[bi * 4 + 2] = c2; rp[bi * 4 + 3] = c3;
            }
        }
        // 5b) warp 15: back-pressure — buf[(t+1)%4] free once all group
        //     consumers have finished reading step t-3 (rflag >= t-2).
        if (s == 15) {
            int tgt = t - 2;
            if (tgt > 0) {
                while (!__all_sync(0xffffffffu, (int)rv >= tgt)) {
                    __nanosleep(16);
                    rv = flag_acquire(grflag);
                }
            }
        }
        __syncthreads();   // C: Red complete AND back-pressure verified

        // 6) finalize: reduce 16 partials, tanh, store.
        {
            float v = 0.f;
            const float* rp = &Red[fp * 17 + fi];
#pragma unroll
            for (int ss = 0; ss < 16; ++ss) v += rp[ss * RED_STRIDE];
            float hv = tanhf(v + xpv);
            g_xp[xpi] = hv;
            hdst[(size_t)(gj0 + fj) * RB + gb0 + fb] = hv;
            if (t == RT - 1)
                out[(size_t)RB * RT * RO + (size_t)(gb0 + fb) * RH + gj0 + fj] = hv;
        }
        __syncthreads();   // D: all h stores done

        // 7) publish write-flag
        if (tid == 0) flag_release(my_wflag, (unsigned)(t + 1));
    }
}

// ---------------------------------------------------------------------------
// Launch
// ---------------------------------------------------------------------------
extern "C" void kernel_launch(void* const* d_in, const int* in_sizes, int n_in,
                              void* d_out, int out_size)
{
    const float* inputs = (const float*)d_in[0];
    const float* h0     = (const float*)d_in[1];
    const float* W_xh   = (const float*)d_in[2];
    const float* W_hh   = (const float*)d_in[3];
    const float* W_hy   = (const float*)d_in[4];
    const float* b_h    = (const float*)d_in[5];
    const float* b_y    = (const float*)d_in[6];
    float* out = (float*)d_out;

    void* xp_ptr = nullptr;
    cudaGetSymbolAddress(&xp_ptr, g_xp);
    float* xp = (float*)xp_ptr;

    cudaFuncSetAttribute(rnn_scan_kernel,
                         cudaFuncAttributeMaxDynamicSharedMemorySize,
                         SMEM_FLOATS * (int)sizeof(float));

    // 0) reset flags, seed h0 (transposed)
    rnn_init<<<257, 256>>>(h0);

    // 1) x_proj = inputs @ W_xh + b_h   (tf32 TC)
    gemm_tf32_bias<<<dim3(RH / 128, (RB * RT) / 128), 256>>>(
        RB * RT, RH, RI, inputs, W_xh, b_h, xp);

    // 2) persistent recurrent scan (fp32, flag-synced, 4-deep ring)
    rnn_scan_kernel<<<128, SCAN_THREADS, SMEM_FLOATS * sizeof(float)>>>(W_hh, out);

    // 3) outputs = hidden_states @ W_hy + b_y   (tf32 TC)
    gemm_tf32_bias<<<dim3(RO / 128, (RB * RT) / 128), 256>>>(
        RB * RT, RO, RH, xp, W_hy, b_y, out);
}

// round 6
// speedup vs baseline: 1.9155x; 1.2287x over previous
#include <cuda_runtime.h>
#include <cuda_bf16.h>
#include <cstdint>
#include <cstddef>

// Problem constants
#define RB 64      // batch
#define RT 512     // time steps
#define RI 512     // input dim
#define RH 1024    // hidden dim
#define RO 512     // output dim
#define NBUF 4     // h ring-buffer depth

// ---------------------------------------------------------------------------
// Scratch (device globals; no allocation allowed)
// ---------------------------------------------------------------------------
__device__ float g_xp[(size_t)RB * RT * RH];     // x_proj, then hidden states (in place)
__device__ unsigned g_hp_hi[NBUF * 512 * 64];    // h as bf16 PAIRS (k even low, k odd high), hi part
__device__ unsigned g_hp_lo[NBUF * 512 * 64];    // lo part. layout [buf][k2][b]
__device__ unsigned g_wflag[128 * 32];           // per-CTA write flags, 128B apart
__device__ unsigned g_rflag[128 * 32];           // per-CTA read  flags, 128B apart

// ---------------------------------------------------------------------------
// Helpers
// ---------------------------------------------------------------------------
__device__ __forceinline__ unsigned to_tf32(float f) {
    unsigned u;
    asm("cvt.rna.tf32.f32 %0,%1;" : "=r"(u) : "f"(f));
    return u;
}
__device__ __forceinline__ void mma_tf32(float* d,
                                         const unsigned* a, const unsigned* b,
                                         const float* c) {
    asm("mma.sync.aligned.m16n8k8.row.col.f32.tf32.tf32.f32 "
        "{%0,%1,%2,%3},{%4,%5,%6,%7},{%8,%9},{%10,%11,%12,%13};"
        : "=f"(d[0]), "=f"(d[1]), "=f"(d[2]), "=f"(d[3])
        : "r"(a[0]), "r"(a[1]), "r"(a[2]), "r"(a[3]),
          "r"(b[0]), "r"(b[1]),
          "f"(c[0]), "f"(c[1]), "f"(c[2]), "f"(c[3]));
}
__device__ __forceinline__ void mma_bf16(float* d,
                                         const unsigned* a, unsigned b0, unsigned b1) {
    asm("mma.sync.aligned.m16n8k16.row.col.f32.bf16.bf16.f32 "
        "{%0,%1,%2,%3},{%4,%5,%6,%7},{%8,%9},{%0,%1,%2,%3};"
        : "+f"(d[0]), "+f"(d[1]), "+f"(d[2]), "+f"(d[3])
        : "r"(a[0]), "r"(a[1]), "r"(a[2]), "r"(a[3]),
          "r"(b0), "r"(b1));
}
__device__ __forceinline__ void flag_release(unsigned* p, unsigned v) {
    asm volatile("st.release.gpu.global.u32 [%0],%1;" :: "l"(p), "r"(v) : "memory");
}
__device__ __forceinline__ unsigned flag_acquire(const unsigned* p) {
    unsigned v;
    asm volatile("ld.acquire.gpu.global.u32 %0,[%1];" : "=r"(v) : "l"(p) : "memory");
    return v;
}
// bf16 hi/lo split of an fp32 value
__device__ __forceinline__ void bf16_split(float v, unsigned short& hb, unsigned short& lb) {
    __nv_bfloat16 h = __float2bfloat16_rn(v);
    float r = v - __bfloat162float(h);
    __nv_bfloat16 l = __float2bfloat16_rn(r);
    hb = __bfloat16_as_ushort(h);
    lb = __bfloat16_as_ushort(l);
}

// ---------------------------------------------------------------------------
// Init: zero flags, seed g_hp buf0 from initial_hidden [b][j]
// ---------------------------------------------------------------------------
__global__ void rnn_init(const float* __restrict__ h0) {
    int bid = blockIdx.x;
    if (bid < 128) {
        int idx = bid * 256 + threadIdx.x;      // 0..32767 pairs
        int k2 = idx >> 6;                       // 0..511
        int b  = idx & 63;
        float v0 = h0[b * RH + 2 * k2];
        float v1 = h0[b * RH + 2 * k2 + 1];
        unsigned short h0b, l0b, h1b, l1b;
        bf16_split(v0, h0b, l0b);
        bf16_split(v1, h1b, l1b);
        g_hp_hi[k2 * 64 + b] = (unsigned)h0b | ((unsigned)h1b << 16);
        g_hp_lo[k2 * 64 + b] = (unsigned)l0b | ((unsigned)l1b << 16);
    } else {
        for (int i = threadIdx.x; i < 128 * 32; i += 256) {
            g_wflag[i] = 0;
            g_rflag[i] = 0;
        }
    }
}

// ---------------------------------------------------------------------------
// TF32 tensor-core GEMM with bias (unchanged — known good 309us each)
// ---------------------------------------------------------------------------
#define ASTR 20
#define BSTR 132
__global__ void __launch_bounds__(256) gemm_tf32_bias(
    int M, int N, int K,
    const float* __restrict__ A, const float* __restrict__ B,
    const float* __restrict__ bias, float* __restrict__ C)
{
    __shared__ unsigned As[128 * ASTR];
    __shared__ unsigned Bs[16 * BSTR];

    const int tid  = threadIdx.x;
    const int lane = tid & 31, wid = tid >> 5;
    const int g  = lane >> 2, tg = lane & 3;
    const int wm = (wid & 3) << 5;
    const int wn = (wid >> 2) << 6;
    const int bx = blockIdx.x << 7, by = blockIdx.y << 7;

    const int ar  = tid >> 2, akq = (tid & 3) << 2;
    const float* Ag = A + (size_t)(by + ar) * K + akq;
    const int bk = tid >> 5, bc = (tid & 31) << 2;
    const float* Bg = B + (size_t)bk * N + bx + bc;

    float4 pa0 = *(const float4*)(Ag);
    float4 pa1 = *(const float4*)(Ag + (size_t)64 * K);
    float4 pb0 = *(const float4*)(Bg);
    float4 pb1 = *(const float4*)(Bg + (size_t)8 * N);

    float acc[2][8][4];
#pragma unroll
    for (int i = 0; i < 2; i++)
#pragma unroll
        for (int j = 0; j < 8; j++)
#pragma unroll
            for (int l = 0; l < 4; l++) acc[i][j][l] = 0.f;

    for (int k0 = 0; ; ) {
        {
            uint4 va0 = make_uint4(to_tf32(pa0.x), to_tf32(pa0.y), to_tf32(pa0.z), to_tf32(pa0.w));
            uint4 va1 = make_uint4(to_tf32(pa1.x), to_tf32(pa1.y), to_tf32(pa1.z), to_tf32(pa1.w));
            *(uint4*)&As[ar * ASTR + akq]        = va0;
            *(uint4*)&As[(ar + 64) * ASTR + akq] = va1;
            uint4 vb0 = make_uint4(to_tf32(pb0.x), to_tf32(pb0.y), to_tf32(pb0.z), to_tf32(pb0.w));
            uint4 vb1 = make_uint4(to_tf32(pb1.x), to_tf32(pb1.y), to_tf32(pb1.z), to_tf32(pb1.w));
            *(uint4*)&Bs[bk * BSTR + bc]       = vb0;
            *(uint4*)&Bs[(bk + 8) * BSTR + bc] = vb1;
        }
        __syncthreads();

        bool more = (k0 + 16) < K;
        if (more) {
            pa0 = *(const float4*)(Ag + k0 + 16);
            pa1 = *(const float4*)(Ag + (size_t)64 * K + k0 + 16);
            pb0 = *(const float4*)(Bg + (size_t)(k0 + 16) * N);
            pb1 = *(const float4*)(Bg + (size_t)(k0 + 24) * N);
        }

#pragma unroll
        for (int ks = 0; ks < 16; ks += 8) {
            unsigned af[2][4], bf[8][2];
#pragma unroll
            for (int mt = 0; mt < 2; mt++) {
                int r = wm + (mt << 4) + g;
                af[mt][0] = As[r * ASTR + ks + tg];
                af[mt][1] = As[(r + 8) * ASTR + ks + tg];
                af[mt][2] = As[r * ASTR + ks + tg + 4];
                af[mt][3] = As[(r + 8) * ASTR + ks + tg + 4];
            }
#pragma unroll
            for (int nt = 0; nt < 8; nt++) {
                int c = wn + (nt << 3) + g;
                bf[nt][0] = Bs[(ks + tg) * BSTR + c];
                bf[nt][1] = Bs[(ks + tg + 4) * BSTR + c];
            }
#pragma unroll
            for (int mt = 0; mt < 2; mt++)
#pragma unroll
                for (int nt = 0; nt < 8; nt++)
                    mma_tf32(acc[mt][nt], af[mt], bf[nt], acc[mt][nt]);
        }
        __syncthreads();

        k0 += 16;
        if (!more) break;
    }

#pragma unroll
    for (int mt = 0; mt < 2; mt++) {
        int r0 = by + wm + (mt << 4) + g;
#pragma unroll
        for (int nt = 0; nt < 8; nt++) {
            int col = bx + wn + (nt << 3) + (tg << 1);
            float b0v = bias[col], b1v = bias[col + 1];
            float2 v0 = make_float2(acc[mt][nt][0] + b0v, acc[mt][nt][1] + b1v);
            float2 v1 = make_float2(acc[mt][nt][2] + b0v, acc[mt][nt][3] + b1v);
            *(float2*)&C[(size_t)r0 * N + col]       = v0;
            *(float2*)&C[(size_t)(r0 + 8) * N + col] = v1;
        }
    }
}

// ---------------------------------------------------------------------------
// Persistent recurrent scan, v5: bf16x2 (hi+lo) tensor-core compute.
// 128 CTAs: 4 batch groups (16 b) x 32 col groups (32 j). 512 thr = 16 warps.
// Warp s owns k-slice [64s, 64s+64) -> k2 in [32s,32s+32), 4 chunks of k=16.
// Per chunk, per n-tile: 3 MMAs (hi*hi + hi*lo + lo*hi), fp32 accum.
// h travels via global in bf16-pair format (packed by producers).
// Flag protocol identical to R5 (proven): wflag/rflag + 4-deep ring; spin
// polls (no nanosleep).
//
// SMEM (u32 words):
//   WHI [512][32] swizzled  : 0      .. 16384
//   WLO [512][32] swizzled  : 16384  .. 32768
//   HHI [512][24]           : 32768  .. 45056
//   HLO [512][24]           : 45056  .. 57344   (Red aliases, sync-guarded)
// ---------------------------------------------------------------------------
#define SCAN_THREADS 512
#define SMEM_U32 57344

__global__ void __launch_bounds__(SCAN_THREADS) rnn_scan_kernel(
    const float* __restrict__ W_hh, float* __restrict__ out)
{
    extern __shared__ unsigned smu[];
    unsigned* WHI = smu;
    unsigned* WLO = smu + 16384;
    unsigned* HHI = smu + 32768;
    unsigned* HLO = smu + 45056;
    float*    Red = (float*)(smu + 45056);   // 16*544 floats, aliases HLO

    const int cta = blockIdx.x;
    const int g   = cta >> 5;            // batch group 0..3
    const int cg  = cta & 31;            // col group 0..31
    const int gb0 = g << 4;
    const int gj0 = cg << 5;
    const int tid = threadIdx.x;
    const int lane = tid & 31;
    const int s    = tid >> 5;           // warp id = k-slice
    const int tg   = lane & 3;
    const int r    = lane >> 2;          // 0..7
    const int k2base = s << 5;           // k2 slice start

    // ---- one-time: convert W_hh[:, gj0:gj0+32] to bf16 hi/lo pairs in smem
    for (int i = 0; i < 32; ++i) {
        int idx = i * SCAN_THREADS + tid;     // 0..16383
        int k2 = idx >> 5, j = idx & 31;
        float w0 = W_hh[(size_t)(2 * k2) * RH + gj0 + j];
        float w1 = W_hh[(size_t)(2 * k2 + 1) * RH + gj0 + j];
        unsigned short h0b, l0b, h1b, l1b;
        bf16_split(w0, h0b, l0b);
        bf16_split(w1, h1b, l1b);
        int dst = k2 * 32 + (j ^ ((k2 & 3) << 3));
        WHI[dst] = (unsigned)h0b | ((unsigned)h1b << 16);
        WLO[dst] = (unsigned)l0b | ((unsigned)l1b << 16);
    }

    // finalize mapping: thread o -> (b = o>>5, j = o&31); lanes o,o+1 = (j,j+1)
    const int fb = tid >> 5;             // 0..15
    const int fj = tid & 31;             // 0..31

    const unsigned* prodflag = &g_wflag[((g << 5) + (s << 1) + (lane & 1)) * 32];
    const unsigned* grflag   = &g_rflag[((g << 5) + lane) * 32];
    unsigned* my_wflag = &g_wflag[cta * 32];
    unsigned* my_rflag = &g_rflag[cta * 32];

    __syncthreads();   // W smem ready

    for (int t = 0; t < RT; ++t) {
        const unsigned bsrc = (unsigned)(t & 3) * (512 * 64);
        const unsigned bdst = (unsigned)((t + 1) & 3) * (512 * 64);

        // 1) wait for this warp's 2 producers (wrote step t's h)
        if (t > 0) {
            const unsigned tgt = (unsigned)t;
            while (flag_acquire(prodflag) < tgt) { }
            __syncwarp();
        }

        // 2) load own bf16-pair chunk: k2 in [k2base, k2base+32), 16 batches
        {
            const int k2r = lane >> 2;          // 0..7
            const int bq  = (lane & 3) << 2;    // 0,4,8,12
#pragma unroll
            for (int it = 0; it < 4; ++it) {
                int k2 = k2base + it * 8 + k2r;
                uint4 v = __ldcg((const uint4*)&g_hp_hi[bsrc + k2 * 64 + gb0 + bq]);
                *(uint4*)&HHI[k2 * 24 + bq] = v;
            }
#pragma unroll
            for (int it = 0; it < 4; ++it) {
                int k2 = k2base + it * 8 + k2r;
                uint4 v = __ldcg((const uint4*)&g_hp_lo[bsrc + k2 * 64 + gb0 + bq]);
                *(uint4*)&HLO[k2 * 24 + bq] = v;
            }
        }
        // warp 15: early-load group read-acks
        unsigned rv = 0;
        if (s == 15) rv = flag_acquire(grflag);

        // x_proj prefetch for finalize
        const size_t xpi = ((size_t)(gb0 + fb) * RT + t) * RH + gj0 + fj;
        const float xpv = g_xp[xpi];

        // 3) MMA compute over own chunk (reads only own HHI/HLO region)
        float acc[4][4];
#pragma unroll
        for (int nt = 0; nt < 4; nt++)
#pragma unroll
            for (int l = 0; l < 4; l++) acc[nt][l] = 0.f;

#pragma unroll
        for (int cc = 0; cc < 4; ++cc) {
            const int k2a = k2base + cc * 8 + tg;
            unsigned ah[4], al[4];
            ah[0] = HHI[k2a * 24 + r];
            ah[1] = HHI[k2a * 24 + r + 8];
            ah[2] = HHI[(k2a + 4) * 24 + r];
            ah[3] = HHI[(k2a + 4) * 24 + r + 8];
            al[0] = HLO[k2a * 24 + r];
            al[1] = HLO[k2a * 24 + r + 8];
            al[2] = HLO[(k2a + 4) * 24 + r];
            al[3] = HLO[(k2a + 4) * 24 + r + 8];
#pragma unroll
            for (int nt = 0; nt < 4; ++nt) {
                const int c0 = ((nt << 3) + r) ^ (tg << 3);   // swizzled col; note n-index = r
                unsigned bh0 = WHI[k2a * 32 + c0];
                unsigned bh1 = WHI[(k2a + 4) * 32 + c0];
                unsigned bl0 = WLO[k2a * 32 + c0];
                unsigned bl1 = WLO[(k2a + 4) * 32 + c0];
                mma_bf16(acc[nt], ah, bh0, bh1);
                mma_bf16(acc[nt], ah, bl0, bl1);
                mma_bf16(acc[nt], al, bh0, bh1);
            }
        }
        __syncthreads();   // B: all HHI/HLO reads done; Red may alias

        // 4) publish read-ack
        if (tid == 0) flag_release(my_rflag, (unsigned)(t + 1));

        // 5a) write partials: Red[s*544 + j*17 + b]
        {
            float* rp = Red + s * 544;
#pragma unroll
            for (int nt = 0; nt < 4; ++nt) {
                int j0 = (nt << 3) + (tg << 1);
                rp[j0 * 17 + r]            = acc[nt][0];
                rp[(j0 + 1) * 17 + r]      = acc[nt][1];
                rp[j0 * 17 + r + 8]        = acc[nt][2];
                rp[(j0 + 1) * 17 + r + 8]  = acc[nt][3];
            }
        }
        // 5b) warp 15: back-pressure (buf[(t+1)%4] free once rflags >= t-2)
        if (s == 15) {
            int tgt = t - 2;
            if (tgt > 0) {
                while (!__all_sync(0xffffffffu, (int)rv >= tgt)) {
                    rv = flag_acquire(grflag);
                }
            }
        }
        __syncthreads();   // C: Red complete AND back-pressure verified

        // 6) finalize: reduce 16 partials, tanh, store fp32 + bf16 pairs
        {
            float v = 0.f;
            const float* rp = Red + fj * 17 + fb;
#pragma unroll
            for (int ss = 0; ss < 16; ++ss) v += rp[ss * 544];
            float hv = tanhf(v + xpv);
            g_xp[xpi] = hv;
            if (t == RT - 1)
                out[(size_t)RB * RT * RO + (size_t)(gb0 + fb) * RH + gj0 + fj] = hv;

            unsigned short hb, lb;
            bf16_split(hv, hb, lb);
            unsigned both = (unsigned)hb | ((unsigned)lb << 16);
            unsigned nb = __shfl_down_sync(0xffffffffu, both, 1);
            if ((fj & 1) == 0) {
                unsigned hi_pair = (both & 0xffffu) | ((nb & 0xffffu) << 16);
                unsigned lo_pair = (both >> 16) | (nb & 0xffff0000u);
                int k2g = (cg << 4) + (fj >> 1);
                g_hp_hi[bdst + k2g * 64 + gb0 + fb] = hi_pair;
                g_hp_lo[bdst + k2g * 64 + gb0 + fb] = lo_pair;
            }
        }
        __syncthreads();   // D: all h stores done

        // 7) publish write-flag
        if (tid == 0) flag_release(my_wflag, (unsigned)(t + 1));
    }
}

// ---------------------------------------------------------------------------
// Launch
// ---------------------------------------------------------------------------
extern "C" void kernel_launch(void* const* d_in, const int* in_sizes, int n_in,
                              void* d_out, int out_size)
{
    const float* inputs = (const float*)d_in[0];
    const float* h0     = (const float*)d_in[1];
    const float* W_xh   = (const float*)d_in[2];
    const float* W_hh   = (const float*)d_in[3];
    const float* W_hy   = (const float*)d_in[4];
    const float* b_h    = (const float*)d_in[5];
    const float* b_y    = (const float*)d_in[6];
    float* out = (float*)d_out;

    void* xp_ptr = nullptr;
    cudaGetSymbolAddress(&xp_ptr, g_xp);
    float* xp = (float*)xp_ptr;

    cudaFuncSetAttribute(rnn_scan_kernel,
                         cudaFuncAttributeMaxDynamicSharedMemorySize,
                         SMEM_U32 * (int)sizeof(unsigned));

    // 0) reset flags, seed h0 as bf16 pairs
    rnn_init<<<129, 256>>>(h0);

    // 1) x_proj = inputs @ W_xh + b_h   (tf32 TC)
    gemm_tf32_bias<<<dim3(RH / 128, (RB * RT) / 128), 256>>>(
        RB * RT, RH, RI, inputs, W_xh, b_h, xp);

    // 2) persistent recurrent scan (bf16x2 TC, flag-synced, 4-deep ring)
    rnn_scan_kernel<<<128, SCAN_THREADS, SMEM_U32 * sizeof(unsigned)>>>(W_hh, out);

    // 3) outputs = hidden_states @ W_hy + b_y   (tf32 TC)
    gemm_tf32_bias<<<dim3(RO / 128, (RB * RT) / 128), 256>>>(
        RB * RT, RO, RH, xp, W_hy, b_y, out);
}

// round 7
// speedup vs baseline: 2.1349x; 1.1145x over previous
#include <cuda_runtime.h>
#include <cuda_bf16.h>
#include <cstdint>
#include <cstddef>

// Problem constants
#define RB 64      // batch
#define RT 512     // time steps
#define RI 512     // input dim
#define RH 1024    // hidden dim
#define RO 512     // output dim
#define NBUF 4     // h ring-buffer depth

// ---------------------------------------------------------------------------
// Scratch (device globals; no allocation allowed)
// ---------------------------------------------------------------------------
__device__ float g_xp[(size_t)RB * RT * RH];   // x_proj, then hidden states (in place)
__device__ uint2 g_hp[NBUF * 512 * 64];        // h bf16 pairs: [buf][k2][b] = {hi_pair, lo_pair}
__device__ unsigned g_wflag[128 * 32];         // per-CTA write flags, 128B apart
__device__ unsigned g_rflag[128 * 32];         // per-CTA read  flags, 128B apart

// ---------------------------------------------------------------------------
// Helpers
// ---------------------------------------------------------------------------
__device__ __forceinline__ unsigned to_tf32(float f) {
    unsigned u;
    asm("cvt.rna.tf32.f32 %0,%1;" : "=r"(u) : "f"(f));
    return u;
}
__device__ __forceinline__ void mma_tf32(float* d,
                                         const unsigned* a, const unsigned* b,
                                         const float* c) {
    asm("mma.sync.aligned.m16n8k8.row.col.f32.tf32.tf32.f32 "
        "{%0,%1,%2,%3},{%4,%5,%6,%7},{%8,%9},{%10,%11,%12,%13};"
        : "=f"(d[0]), "=f"(d[1]), "=f"(d[2]), "=f"(d[3])
        : "r"(a[0]), "r"(a[1]), "r"(a[2]), "r"(a[3]),
          "r"(b[0]), "r"(b[1]),
          "f"(c[0]), "f"(c[1]), "f"(c[2]), "f"(c[3]));
}
__device__ __forceinline__ void mma_bf16(float* d,
                                         const unsigned* a, unsigned b0, unsigned b1) {
    asm("mma.sync.aligned.m16n8k16.row.col.f32.bf16.bf16.f32 "
        "{%0,%1,%2,%3},{%4,%5,%6,%7},{%8,%9},{%0,%1,%2,%3};"
        : "+f"(d[0]), "+f"(d[1]), "+f"(d[2]), "+f"(d[3])
        : "r"(a[0]), "r"(a[1]), "r"(a[2]), "r"(a[3]),
          "r"(b0), "r"(b1));
}
__device__ __forceinline__ void flag_release(unsigned* p, unsigned v) {
    asm volatile("st.release.gpu.global.u32 [%0],%1;" :: "l"(p), "r"(v) : "memory");
}
__device__ __forceinline__ unsigned flag_acquire(const unsigned* p) {
    unsigned v;
    asm volatile("ld.acquire.gpu.global.u32 %0,[%1];" : "=r"(v) : "l"(p) : "memory");
    return v;
}
__device__ __forceinline__ void bf16_split(float v, unsigned short& hb, unsigned short& lb) {
    __nv_bfloat16 h = __float2bfloat16_rn(v);
    float r = v - __bfloat162float(h);
    __nv_bfloat16 l = __float2bfloat16_rn(r);
    hb = __bfloat16_as_ushort(h);
    lb = __bfloat16_as_ushort(l);
}
__device__ __forceinline__ uint2 ldcg_u2(const uint2* p) {
    uint2 v;
    asm volatile("ld.global.cg.v2.u32 {%0,%1},[%2];" : "=r"(v.x), "=r"(v.y) : "l"(p));
    return v;
}

// ---------------------------------------------------------------------------
// Init: zero flags, seed g_hp buf0 from initial_hidden [b][j]
// ---------------------------------------------------------------------------
__global__ void rnn_init(const float* __restrict__ h0) {
    int bid = blockIdx.x;
    if (bid < 128) {
        int idx = bid * 256 + threadIdx.x;      // 0..32767 pairs
        int k2 = idx >> 6;                       // 0..511
        int b  = idx & 63;
        float v0 = h0[b * RH + 2 * k2];
        float v1 = h0[b * RH + 2 * k2 + 1];
        unsigned short h0b, l0b, h1b, l1b;
        bf16_split(v0, h0b, l0b);
        bf16_split(v1, h1b, l1b);
        g_hp[k2 * 64 + b] = make_uint2(
            (unsigned)h0b | ((unsigned)h1b << 16),
            (unsigned)l0b | ((unsigned)l1b << 16));
    } else {
        for (int i = threadIdx.x; i < 128 * 32; i += 256) {
            g_wflag[i] = 0;
            g_rflag[i] = 0;
        }
    }
}

// ---------------------------------------------------------------------------
// TF32 tensor-core GEMM with bias (unchanged — known good 309us each)
// ---------------------------------------------------------------------------
#define ASTR 20
#define BSTR 132
__global__ void __launch_bounds__(256) gemm_tf32_bias(
    int M, int N, int K,
    const float* __restrict__ A, const float* __restrict__ B,
    const float* __restrict__ bias, float* __restrict__ C)
{
    __shared__ unsigned As[128 * ASTR];
    __shared__ unsigned Bs[16 * BSTR];

    const int tid  = threadIdx.x;
    const int lane = tid & 31, wid = tid >> 5;
    const int g  = lane >> 2, tg = lane & 3;
    const int wm = (wid & 3) << 5;
    const int wn = (wid >> 2) << 6;
    const int bx = blockIdx.x << 7, by = blockIdx.y << 7;

    const int ar  = tid >> 2, akq = (tid & 3) << 2;
    const float* Ag = A + (size_t)(by + ar) * K + akq;
    const int bk = tid >> 5, bc = (tid & 31) << 2;
    const float* Bg = B + (size_t)bk * N + bx + bc;

    float4 pa0 = *(const float4*)(Ag);
    float4 pa1 = *(const float4*)(Ag + (size_t)64 * K);
    float4 pb0 = *(const float4*)(Bg);
    float4 pb1 = *(const float4*)(Bg + (size_t)8 * N);

    float acc[2][8][4];
#pragma unroll
    for (int i = 0; i < 2; i++)
#pragma unroll
        for (int j = 0; j < 8; j++)
#pragma unroll
            for (int l = 0; l < 4; l++) acc[i][j][l] = 0.f;

    for (int k0 = 0; ; ) {
        {
            uint4 va0 = make_uint4(to_tf32(pa0.x), to_tf32(pa0.y), to_tf32(pa0.z), to_tf32(pa0.w));
            uint4 va1 = make_uint4(to_tf32(pa1.x), to_tf32(pa1.y), to_tf32(pa1.z), to_tf32(pa1.w));
            *(uint4*)&As[ar * ASTR + akq]        = va0;
            *(uint4*)&As[(ar + 64) * ASTR + akq] = va1;
            uint4 vb0 = make_uint4(to_tf32(pb0.x), to_tf32(pb0.y), to_tf32(pb0.z), to_tf32(pb0.w));
            uint4 vb1 = make_uint4(to_tf32(pb1.x), to_tf32(pb1.y), to_tf32(pb1.z), to_tf32(pb1.w));
            *(uint4*)&Bs[bk * BSTR + bc]       = vb0;
            *(uint4*)&Bs[(bk + 8) * BSTR + bc] = vb1;
        }
        __syncthreads();

        bool more = (k0 + 16) < K;
        if (more) {
            pa0 = *(const float4*)(Ag + k0 + 16);
            pa1 = *(const float4*)(Ag + (size_t)64 * K + k0 + 16);
            pb0 = *(const float4*)(Bg + (size_t)(k0 + 16) * N);
            pb1 = *(const float4*)(Bg + (size_t)(k0 + 24) * N);
        }

#pragma unroll
        for (int ks = 0; ks < 16; ks += 8) {
            unsigned af[2][4], bf[8][2];
#pragma unroll
            for (int mt = 0; mt < 2; mt++) {
                int r = wm + (mt << 4) + g;
                af[mt][0] = As[r * ASTR + ks + tg];
                af[mt][1] = As[(r + 8) * ASTR + ks + tg];
                af[mt][2] = As[r * ASTR + ks + tg + 4];
                af[mt][3] = As[(r + 8) * ASTR + ks + tg + 4];
            }
#pragma unroll
            for (int nt = 0; nt < 8; nt++) {
                int c = wn + (nt << 3) + g;
                bf[nt][0] = Bs[(ks + tg) * BSTR + c];
                bf[nt][1] = Bs[(ks + tg + 4) * BSTR + c];
            }
#pragma unroll
            for (int mt = 0; mt < 2; mt++)
#pragma unroll
                for (int nt = 0; nt < 8; nt++)
                    mma_tf32(acc[mt][nt], af[mt], bf[nt], acc[mt][nt]);
        }
        __syncthreads();

        k0 += 16;
        if (!more) break;
    }

#pragma unroll
    for (int mt = 0; mt < 2; mt++) {
        int r0 = by + wm + (mt << 4) + g;
#pragma unroll
        for (int nt = 0; nt < 8; nt++) {
            int col = bx + wn + (nt << 3) + (tg << 1);
            float b0v = bias[col], b1v = bias[col + 1];
            float2 v0 = make_float2(acc[mt][nt][0] + b0v, acc[mt][nt][1] + b1v);
            float2 v1 = make_float2(acc[mt][nt][2] + b0v, acc[mt][nt][3] + b1v);
            *(float2*)&C[(size_t)r0 * N + col]       = v0;
            *(float2*)&C[(size_t)(r0 + 8) * N + col] = v1;
        }
    }
}

// ---------------------------------------------------------------------------
// Persistent recurrent scan, v6: direct global->register A-fragments.
// 128 CTAs: 4 batch groups (16 b) x 32 col groups (32 j). 512 thr = 16 warps.
// h exchanged via global as interleaved uint2{hi_pair, lo_pair}; each warp
// LDG.64s its own MMA fragments directly (no smem staging). Red dedicated.
// 2 syncthreads/step. Flag protocol identical to R5/R6 (proven).
//
// SMEM (u32 words): WHI[512*32] swz | WLO[512*32] swz | Red 16*544 floats
// ---------------------------------------------------------------------------
#define SCAN_THREADS 512
#define SMEM_U32 (16384 + 16384 + 16*544)

__global__ void __launch_bounds__(SCAN_THREADS) rnn_scan_kernel(
    const float* __restrict__ W_hh, float* __restrict__ out)
{
    extern __shared__ unsigned smu[];
    unsigned* WHI = smu;
    unsigned* WLO = smu + 16384;
    float*    Red = (float*)(smu + 32768);   // dedicated: no aliasing

    const int cta = blockIdx.x;
    const int g   = cta >> 5;            // batch group 0..3
    const int cg  = cta & 31;            // col group 0..31
    const int gb0 = g << 4;
    const int gj0 = cg << 5;
    const int tid = threadIdx.x;
    const int lane = tid & 31;
    const int s    = tid >> 5;           // warp id = k-slice
    const int tg   = lane & 3;
    const int r    = lane >> 2;          // 0..7
    const int k2base = s << 5;

    // one-time: convert W_hh[:, gj0:gj0+32] to bf16 hi/lo pairs in smem (swizzled)
    for (int i = 0; i < 32; ++i) {
        int idx = i * SCAN_THREADS + tid;
        int k2 = idx >> 5, j = idx & 31;
        float w0 = W_hh[(size_t)(2 * k2) * RH + gj0 + j];
        float w1 = W_hh[(size_t)(2 * k2 + 1) * RH + gj0 + j];
        unsigned short h0b, l0b, h1b, l1b;
        bf16_split(w0, h0b, l0b);
        bf16_split(w1, h1b, l1b);
        int dst = k2 * 32 + (j ^ ((k2 & 3) << 3));
        WHI[dst] = (unsigned)h0b | ((unsigned)h1b << 16);
        WLO[dst] = (unsigned)l0b | ((unsigned)l1b << 16);
    }

    // finalize mapping
    const int fb = tid >> 5;             // 0..15
    const int fj = tid & 31;             // 0..31

    const unsigned* prodflag = &g_wflag[((g << 5) + (s << 1) + (lane & 1)) * 32];
    const unsigned* grflag   = &g_rflag[((g << 5) + lane) * 32];
    unsigned* my_wflag = &g_wflag[cta * 32];
    unsigned* my_rflag = &g_rflag[cta * 32];

    __syncthreads();   // W smem ready

    for (int t = 0; t < RT; ++t) {
        const unsigned bsrc = (unsigned)(t & 3) * (512 * 64);
        const unsigned bdst = (unsigned)((t + 1) & 3) * (512 * 64);

        // x_proj prefetch (independent of flags)
        const size_t xpi = ((size_t)(gb0 + fb) * RT + t) * RH + gj0 + fj;
        const float xpv = g_xp[xpi];

        // 1) wait for this warp's 2 producers
        if (t > 0) {
            const unsigned tgt = (unsigned)t;
            while (flag_acquire(prodflag) < tgt) { }
            __syncwarp();
        }
        // warp 15: early-load group read-acks
        unsigned rv = 0;
        if (s == 15) rv = flag_acquire(grflag);

        // 2) direct LDG of all A-fragments (16 x LDG.64, high MLP)
        unsigned ah[4][4], al[4][4];
#pragma unroll
        for (int cc = 0; cc < 4; ++cc) {
            const int k2a = k2base + (cc << 3) + tg;
            uint2 v0 = ldcg_u2(&g_hp[bsrc + k2a * 64 + gb0 + r]);
            uint2 v1 = ldcg_u2(&g_hp[bsrc + k2a * 64 + gb0 + r + 8]);
            uint2 v2 = ldcg_u2(&g_hp[bsrc + (k2a + 4) * 64 + gb0 + r]);
            uint2 v3 = ldcg_u2(&g_hp[bsrc + (k2a + 4) * 64 + gb0 + r + 8]);
            ah[cc][0] = v0.x; al[cc][0] = v0.y;
            ah[cc][1] = v1.x; al[cc][1] = v1.y;
            ah[cc][2] = v2.x; al[cc][2] = v2.y;
            ah[cc][3] = v3.x; al[cc][3] = v3.y;
        }

        // 3) MMA compute (hi*hi + hi*lo + lo*hi), fp32 accum
        float acc[4][4];
#pragma unroll
        for (int nt = 0; nt < 4; nt++)
#pragma unroll
            for (int l = 0; l < 4; l++) acc[nt][l] = 0.f;

#pragma unroll
        for (int cc = 0; cc < 4; ++cc) {
            const int k2a = k2base + (cc << 3) + tg;
#pragma unroll
            for (int nt = 0; nt < 4; ++nt) {
                const int c0 = ((nt << 3) + r) ^ (tg << 3);
                unsigned bh0 = WHI[k2a * 32 + c0];
                unsigned bh1 = WHI[(k2a + 4) * 32 + c0];
                unsigned bl0 = WLO[k2a * 32 + c0];
                unsigned bl1 = WLO[(k2a + 4) * 32 + c0];
                mma_bf16(acc[nt], ah[cc], bh0, bh1);
                mma_bf16(acc[nt], ah[cc], bl0, bl1);
                mma_bf16(acc[nt], al[cc], bh0, bh1);
            }
        }

        // 4) write partials: Red[s*544 + j*17 + b]
        {
            float* rp = Red + s * 544;
#pragma unroll
            for (int nt = 0; nt < 4; ++nt) {
                int j0 = (nt << 3) + (tg << 1);
                rp[j0 * 17 + r]            = acc[nt][0];
                rp[(j0 + 1) * 17 + r]      = acc[nt][1];
                rp[j0 * 17 + r + 8]        = acc[nt][2];
                rp[(j0 + 1) * 17 + r + 8]  = acc[nt][3];
            }
        }
        // 5) warp 15: back-pressure — buf[(t+1)%4] free once rflags >= t-2
        if (s == 15) {
            int tgt = t - 2;
            if (tgt > 0) {
                while (!__all_sync(0xffffffffu, (int)rv >= tgt)) {
                    rv = flag_acquire(grflag);
                }
            }
        }
        __syncthreads();   // C: Red complete, back-pressure verified, LDGs consumed

        // 6) publish read-ack (all reads of buf[t%4] done at syncC)
        if (tid == 0) flag_release(my_rflag, (unsigned)(t + 1));

        // 7) finalize: reduce 16 partials, tanh, store
        {
            float v = 0.f;
            const float* rp = Red + fj * 17 + fb;
#pragma unroll
            for (int ss = 0; ss < 16; ++ss) v += rp[ss * 544];
            float hv = tanhf(v + xpv);
            g_xp[xpi] = hv;
            if (t == RT - 1)
                out[(size_t)RB * RT * RO + (size_t)(gb0 + fb) * RH + gj0 + fj] = hv;

            unsigned short hb, lb;
            bf16_split(hv, hb, lb);
            unsigned both = (unsigned)hb | ((unsigned)lb << 16);
            unsigned nb = __shfl_down_sync(0xffffffffu, both, 1);
            if ((fj & 1) == 0) {
                unsigned hi_pair = (both & 0xffffu) | ((nb & 0xffffu) << 16);
                unsigned lo_pair = (both >> 16) | (nb & 0xffff0000u);
                int k2g = (cg << 4) + (fj >> 1);
                g_hp[bdst + k2g * 64 + gb0 + fb] = make_uint2(hi_pair, lo_pair);
            }
        }
        __syncthreads();   // D: all h stores done

        // 8) publish write-flag
        if (tid == 0) flag_release(my_wflag, (unsigned)(t + 1));
    }
}

// ---------------------------------------------------------------------------
// Launch
// ---------------------------------------------------------------------------
extern "C" void kernel_launch(void* const* d_in, const int* in_sizes, int n_in,
                              void* d_out, int out_size)
{
    const float* inputs = (const float*)d_in[0];
    const float* h0     = (const float*)d_in[1];
    const float* W_xh   = (const float*)d_in[2];
    const float* W_hh   = (const float*)d_in[3];
    const float* W_hy   = (const float*)d_in[4];
    const float* b_h    = (const float*)d_in[5];
    const float* b_y    = (const float*)d_in[6];
    float* out = (float*)d_out;

    void* xp_ptr = nullptr;
    cudaGetSymbolAddress(&xp_ptr, g_xp);
    float* xp = (float*)xp_ptr;

    cudaFuncSetAttribute(rnn_scan_kernel,
                         cudaFuncAttributeMaxDynamicSharedMemorySize,
                         SMEM_U32 * (int)sizeof(unsigned));

    // 0) reset flags, seed h0 as bf16 pairs
    rnn_init<<<129, 256>>>(h0);

    // 1) x_proj = inputs @ W_xh + b_h   (tf32 TC)
    gemm_tf32_bias<<<dim3(RH / 128, (RB * RT) / 128), 256>>>(
        RB * RT, RH, RI, inputs, W_xh, b_h, xp);

    // 2) persistent recurrent scan (bf16x2 TC, direct-LDG fragments)
    rnn_scan_kernel<<<128, SCAN_THREADS, SMEM_U32 * sizeof(unsigned)>>>(W_hh, out);

    // 3) outputs = hidden_states @ W_hy + b_y   (tf32 TC)
    gemm_tf32_bias<<<dim3(RO / 128, (RB * RT) / 128), 256>>>(
        RB * RT, RO, RH, xp, W_hy, b_y, out);
}

// round 8
// speedup vs baseline: 2.2476x; 1.0528x over previous
#include <cuda_runtime.h>
#include <cuda_bf16.h>
#include <cuda_fp16.h>
#include <cstdint>
#include <cstddef>

// Problem constants
#define RB 64      // batch
#define RT 512     // time steps
#define RI 512     // input dim
#define RH 1024    // hidden dim
#define RO 512     // output dim
#define NBUF 4     // h ring-buffer depth

// ---------------------------------------------------------------------------
// Scratch (device globals; no allocation allowed)
// ---------------------------------------------------------------------------
__device__ float g_xp[(size_t)RB * RT * RH];   // x_proj, then hidden states (in place)
__device__ uint2 g_hp[NBUF * 512 * 64];        // h fp16 pairs: [buf][k2][b] = {hi_pair, lo_pair}
__device__ unsigned g_wflag[128 * 32];         // per-CTA write flags, 128B apart
__device__ unsigned g_rflag[128 * 32];         // per-CTA read  flags, 128B apart

// ---------------------------------------------------------------------------
// Helpers
// ---------------------------------------------------------------------------
__device__ __forceinline__ unsigned to_tf32(float f) {
    unsigned u;
    asm("cvt.rna.tf32.f32 %0,%1;" : "=r"(u) : "f"(f));
    return u;
}
__device__ __forceinline__ void mma_tf32(float* d,
                                         const unsigned* a, const unsigned* b,
                                         const float* c) {
    asm("mma.sync.aligned.m16n8k8.row.col.f32.tf32.tf32.f32 "
        "{%0,%1,%2,%3},{%4,%5,%6,%7},{%8,%9},{%10,%11,%12,%13};"
        : "=f"(d[0]), "=f"(d[1]), "=f"(d[2]), "=f"(d[3])
        : "r"(a[0]), "r"(a[1]), "r"(a[2]), "r"(a[3]),
          "r"(b[0]), "r"(b[1]),
          "f"(c[0]), "f"(c[1]), "f"(c[2]), "f"(c[3]));
}
// fp16 m16n8k16 MMA, fp32 accumulate (same fragment layout as bf16 variant)
__device__ __forceinline__ void mma_f16(float* d,
                                        const unsigned* a, unsigned b0, unsigned b1) {
    asm("mma.sync.aligned.m16n8k16.row.col.f32.f16.f16.f32 "
        "{%0,%1,%2,%3},{%4,%5,%6,%7},{%8,%9},{%0,%1,%2,%3};"
        : "+f"(d[0]), "+f"(d[1]), "+f"(d[2]), "+f"(d[3])
        : "r"(a[0]), "r"(a[1]), "r"(a[2]), "r"(a[3]),
          "r"(b0), "r"(b1));
}
__device__ __forceinline__ void flag_release(unsigned* p, unsigned v) {
    asm volatile("st.release.gpu.global.u32 [%0],%1;" :: "l"(p), "r"(v) : "memory");
}
__device__ __forceinline__ unsigned flag_acquire(const unsigned* p) {
    unsigned v;
    asm volatile("ld.acquire.gpu.global.u32 %0,[%1];" : "=r"(v) : "l"(p) : "memory");
    return v;
}
// fp16 hi/lo split of an fp32 value (|v| <= ~1, range-safe)
__device__ __forceinline__ void f16_split(float v, unsigned short& hb, unsigned short& lb) {
    __half h = __float2half_rn(v);
    float r = v - __half2float(h);
    __half l = __float2half_rn(r);
    hb = __half_as_ushort(h);
    lb = __half_as_ushort(l);
}
__device__ __forceinline__ uint2 ldcg_u2(const uint2* p) {
    uint2 v;
    asm volatile("ld.global.cg.v2.u32 {%0,%1},[%2];" : "=r"(v.x), "=r"(v.y) : "l"(p));
    return v;
}

// ---------------------------------------------------------------------------
// Init: zero flags, seed g_hp buf0 from initial_hidden [b][j]
// ---------------------------------------------------------------------------
__global__ void rnn_init(const float* __restrict__ h0) {
    int bid = blockIdx.x;
    if (bid < 128) {
        int idx = bid * 256 + threadIdx.x;      // 0..32767 pairs
        int k2 = idx >> 6;                       // 0..511
        int b  = idx & 63;
        float v0 = h0[b * RH + 2 * k2];
        float v1 = h0[b * RH + 2 * k2 + 1];
        unsigned short h0b, l0b, h1b, l1b;
        f16_split(v0, h0b, l0b);
        f16_split(v1, h1b, l1b);
        g_hp[k2 * 64 + b] = make_uint2(
            (unsigned)h0b | ((unsigned)h1b << 16),
            (unsigned)l0b | ((unsigned)l1b << 16));
    } else {
        for (int i = threadIdx.x; i < 128 * 32; i += 256) {
            g_wflag[i] = 0;
            g_rflag[i] = 0;
        }
    }
}

// ---------------------------------------------------------------------------
// TF32 tensor-core GEMM with bias (unchanged — known good 309us each)
// ---------------------------------------------------------------------------
#define ASTR 20
#define BSTR 132
__global__ void __launch_bounds__(256) gemm_tf32_bias(
    int M, int N, int K,
    const float* __restrict__ A, const float* __restrict__ B,
    const float* __restrict__ bias, float* __restrict__ C)
{
    __shared__ unsigned As[128 * ASTR];
    __shared__ unsigned Bs[16 * BSTR];

    const int tid  = threadIdx.x;
    const int lane = tid & 31, wid = tid >> 5;
    const int g  = lane >> 2, tg = lane & 3;
    const int wm = (wid & 3) << 5;
    const int wn = (wid >> 2) << 6;
    const int bx = blockIdx.x << 7, by = blockIdx.y << 7;

    const int ar  = tid >> 2, akq = (tid & 3) << 2;
    const float* Ag = A + (size_t)(by + ar) * K + akq;
    const int bk = tid >> 5, bc = (tid & 31) << 2;
    const float* Bg = B + (size_t)bk * N + bx + bc;

    float4 pa0 = *(const float4*)(Ag);
    float4 pa1 = *(const float4*)(Ag + (size_t)64 * K);
    float4 pb0 = *(const float4*)(Bg);
    float4 pb1 = *(const float4*)(Bg + (size_t)8 * N);

    float acc[2][8][4];
#pragma unroll
    for (int i = 0; i < 2; i++)
#pragma unroll
        for (int j = 0; j < 8; j++)
#pragma unroll
            for (int l = 0; l < 4; l++) acc[i][j][l] = 0.f;

    for (int k0 = 0; ; ) {
        {
            uint4 va0 = make_uint4(to_tf32(pa0.x), to_tf32(pa0.y), to_tf32(pa0.z), to_tf32(pa0.w));
            uint4 va1 = make_uint4(to_tf32(pa1.x), to_tf32(pa1.y), to_tf32(pa1.z), to_tf32(pa1.w));
            *(uint4*)&As[ar * ASTR + akq]        = va0;
            *(uint4*)&As[(ar + 64) * ASTR + akq] = va1;
            uint4 vb0 = make_uint4(to_tf32(pb0.x), to_tf32(pb0.y), to_tf32(pb0.z), to_tf32(pb0.w));
            uint4 vb1 = make_uint4(to_tf32(pb1.x), to_tf32(pb1.y), to_tf32(pb1.z), to_tf32(pb1.w));
            *(uint4*)&Bs[bk * BSTR + bc]       = vb0;
            *(uint4*)&Bs[(bk + 8) * BSTR + bc] = vb1;
        }
        __syncthreads();

        bool more = (k0 + 16) < K;
        if (more) {
            pa0 = *(const float4*)(Ag + k0 + 16);
            pa1 = *(const float4*)(Ag + (size_t)64 * K + k0 + 16);
            pb0 = *(const float4*)(Bg + (size_t)(k0 + 16) * N);
            pb1 = *(const float4*)(Bg + (size_t)(k0 + 24) * N);
        }

#pragma unroll
        for (int ks = 0; ks < 16; ks += 8) {
            unsigned af[2][4], bf[8][2];
#pragma unroll
            for (int mt = 0; mt < 2; mt++) {
                int r = wm + (mt << 4) + g;
                af[mt][0] = As[r * ASTR + ks + tg];
                af[mt][1] = As[(r + 8) * ASTR + ks + tg];
                af[mt][2] = As[r * ASTR + ks + tg + 4];
                af[mt][3] = As[(r + 8) * ASTR + ks + tg + 4];
            }
#pragma unroll
            for (int nt = 0; nt < 8; nt++) {
                int c = wn + (nt << 3) + g;
                bf[nt][0] = Bs[(ks + tg) * BSTR + c];
                bf[nt][1] = Bs[(ks + tg + 4) * BSTR + c];
            }
#pragma unroll
            for (int mt = 0; mt < 2; mt++)
#pragma unroll
                for (int nt = 0; nt < 8; nt++)
                    mma_tf32(acc[mt][nt], af[mt], bf[nt], acc[mt][nt]);
        }
        __syncthreads();

        k0 += 16;
        if (!more) break;
    }

#pragma unroll
    for (int mt = 0; mt < 2; mt++) {
        int r0 = by + wm + (mt << 4) + g;
#pragma unroll
        for (int nt = 0; nt < 8; nt++) {
            int col = bx + wn + (nt << 3) + (tg << 1);
            float b0v = bias[col], b1v = bias[col + 1];
            float2 v0 = make_float2(acc[mt][nt][0] + b0v, acc[mt][nt][1] + b1v);
            float2 v1 = make_float2(acc[mt][nt][2] + b0v, acc[mt][nt][3] + b1v);
            *(float2*)&C[(size_t)r0 * N + col]       = v0;
            *(float2*)&C[(size_t)(r0 + 8) * N + col] = v1;
        }
    }
}

// ---------------------------------------------------------------------------
// Persistent recurrent scan, v7: fp16-pair h x single-fp16 W -> 32 MMAs/warp.
// h = h_hi + h_lo (fp16 pair, ~exact since |h|<=1); W_hh quantized to one
// fp16 (rel err ~1e-4, contractive recurrence). Per chunk/nt: 2 MMAs
// (W*h_hi + W*h_lo) vs 3 in the bf16x2 version. Fragment indexing identical
// to R6/R7 (proven). Flag protocol identical to R5-R7 (proven).
//
// SMEM (u32 words): W2[512*32] swizzled fp16-pairs (64KB) | Red 16*544 floats
// ---------------------------------------------------------------------------
#define SCAN_THREADS 512
#define SMEM_U32 (16384 + 16*544)

__global__ void __launch_bounds__(SCAN_THREADS) rnn_scan_kernel(
    const float* __restrict__ W_hh, float* __restrict__ out)
{
    extern __shared__ unsigned smu[];
    unsigned* W2  = smu;                     // [k2=512][32j] fp16x2, swizzled
    float*    Red = (float*)(smu + 16384);   // 16*544 floats, dedicated

    const int cta = blockIdx.x;
    const int g   = cta >> 5;            // batch group 0..3
    const int cg  = cta & 31;            // col group 0..31
    const int gb0 = g << 4;
    const int gj0 = cg << 5;
    const int tid = threadIdx.x;
    const int lane = tid & 31;
    const int s    = tid >> 5;           // warp id = k-slice
    const int tg   = lane & 3;
    const int r    = lane >> 2;          // 0..7
    const int k2base = s << 5;

    // one-time: convert W_hh[:, gj0:gj0+32] to fp16 k-pairs in smem (swizzled)
    for (int i = 0; i < 32; ++i) {
        int idx = i * SCAN_THREADS + tid;
        int k2 = idx >> 5, j = idx & 31;
        float w0 = W_hh[(size_t)(2 * k2) * RH + gj0 + j];
        float w1 = W_hh[(size_t)(2 * k2 + 1) * RH + gj0 + j];
        unsigned short a = __half_as_ushort(__float2half_rn(w0));
        unsigned short b = __half_as_ushort(__float2half_rn(w1));
        int dst = k2 * 32 + (j ^ ((k2 & 3) << 3));
        W2[dst] = (unsigned)a | ((unsigned)b << 16);
    }

    // finalize mapping
    const int fb = tid >> 5;             // 0..15
    const int fj = tid & 31;             // 0..31

    const unsigned* prodflag = &g_wflag[((g << 5) + (s << 1) + (lane & 1)) * 32];
    const unsigned* grflag   = &g_rflag[((g << 5) + lane) * 32];
    unsigned* my_wflag = &g_wflag[cta * 32];
    unsigned* my_rflag = &g_rflag[cta * 32];

    __syncthreads();   // W smem ready

    for (int t = 0; t < RT; ++t) {
        const unsigned bsrc = (unsigned)(t & 3) * (512 * 64);
        const unsigned bdst = (unsigned)((t + 1) & 3) * (512 * 64);

        // x_proj prefetch (independent of flags)
        const size_t xpi = ((size_t)(gb0 + fb) * RT + t) * RH + gj0 + fj;
        const float xpv = g_xp[xpi];

        // 1) wait for this warp's 2 producers
        if (t > 0) {
            const unsigned tgt = (unsigned)t;
            while (flag_acquire(prodflag) < tgt) { }
            __syncwarp();
        }
        // warp 15: early-load group read-acks
        unsigned rv = 0;
        if (s == 15) rv = flag_acquire(grflag);

        // 2) direct LDG of all A-fragments (16 x LDG.64, high MLP)
        unsigned ah[4][4], al[4][4];
#pragma unroll
        for (int cc = 0; cc < 4; ++cc) {
            const int k2a = k2base + (cc << 3) + tg;
            uint2 v0 = ldcg_u2(&g_hp[bsrc + k2a * 64 + gb0 + r]);
            uint2 v1 = ldcg_u2(&g_hp[bsrc + k2a * 64 + gb0 + r + 8]);
            uint2 v2 = ldcg_u2(&g_hp[bsrc + (k2a + 4) * 64 + gb0 + r]);
            uint2 v3 = ldcg_u2(&g_hp[bsrc + (k2a + 4) * 64 + gb0 + r + 8]);
            ah[cc][0] = v0.x; al[cc][0] = v0.y;
            ah[cc][1] = v1.x; al[cc][1] = v1.y;
            ah[cc][2] = v2.x; al[cc][2] = v2.y;
            ah[cc][3] = v3.x; al[cc][3] = v3.y;
        }

        // 3) MMA compute: W*(h_hi) + W*(h_lo), fp32 accum. 32 MMAs/warp.
        float acc[4][4];
#pragma unroll
        for (int nt = 0; nt < 4; nt++)
#pragma unroll
            for (int l = 0; l < 4; l++) acc[nt][l] = 0.f;

#pragma unroll
        for (int cc = 0; cc < 4; ++cc) {
            const int k2a = k2base + (cc << 3) + tg;
#pragma unroll
            for (int nt = 0; nt < 4; ++nt) {
                const int c0 = ((nt << 3) + r) ^ (tg << 3);
                unsigned b0 = W2[k2a * 32 + c0];
                unsigned b1 = W2[(k2a + 4) * 32 + c0];
                mma_f16(acc[nt], ah[cc], b0, b1);
                mma_f16(acc[nt], al[cc], b0, b1);
            }
        }

        // 4) write partials: Red[s*544 + j*17 + b]
        {
            float* rp = Red + s * 544;
#pragma unroll
            for (int nt = 0; nt < 4; ++nt) {
                int j0 = (nt << 3) + (tg << 1);
                rp[j0 * 17 + r]            = acc[nt][0];
                rp[(j0 + 1) * 17 + r]      = acc[nt][1];
                rp[j0 * 17 + r + 8]        = acc[nt][2];
                rp[(j0 + 1) * 17 + r + 8]  = acc[nt][3];
            }
        }
        // 5) warp 15: back-pressure — buf[(t+1)%4] free once rflags >= t-2
        if (s == 15) {
            int tgt = t - 2;
            if (tgt > 0) {
                while (!__all_sync(0xffffffffu, (int)rv >= tgt)) {
                    rv = flag_acquire(grflag);
                }
            }
        }
        __syncthreads();   // C: Red complete, back-pressure verified, LDGs consumed

        // 6) publish read-ack (all reads of buf[t%4] done at syncC)
        if (tid == 0) flag_release(my_rflag, (unsigned)(t + 1));

        // 7) finalize: reduce 16 partials, tanh, store
        {
            float v = 0.f;
            const float* rp = Red + fj * 17 + fb;
#pragma unroll
            for (int ss = 0; ss < 16; ++ss) v += rp[ss * 544];
            float hv = tanhf(v + xpv);
            g_xp[xpi] = hv;
            if (t == RT - 1)
                out[(size_t)RB * RT * RO + (size_t)(gb0 + fb) * RH + gj0 + fj] = hv;

            unsigned short hb, lb;
            f16_split(hv, hb, lb);
            unsigned both = (unsigned)hb | ((unsigned)lb << 16);
            unsigned nb = __shfl_down_sync(0xffffffffu, both, 1);
            if ((fj & 1) == 0) {
                unsigned hi_pair = (both & 0xffffu) | ((nb & 0xffffu) << 16);
                unsigned lo_pair = (both >> 16) | (nb & 0xffff0000u);
                int k2g = (cg << 4) + (fj >> 1);
                g_hp[bdst + k2g * 64 + gb0 + fb] = make_uint2(hi_pair, lo_pair);
            }
        }
        __syncthreads();   // D: all h stores done

        // 8) publish write-flag
        if (tid == 0) flag_release(my_wflag, (unsigned)(t + 1));
    }
}

// ---------------------------------------------------------------------------
// Launch
// ---------------------------------------------------------------------------
extern "C" void kernel_launch(void* const* d_in, const int* in_sizes, int n_in,
                              void* d_out, int out_size)
{
    const float* inputs = (const float*)d_in[0];
    const float* h0     = (const float*)d_in[1];
    const float* W_xh   = (const float*)d_in[2];
    const float* W_hh   = (const float*)d_in[3];
    const float* W_hy   = (const float*)d_in[4];
    const float* b_h    = (const float*)d_in[5];
    const float* b_y    = (const float*)d_in[6];
    float* out = (float*)d_out;

    void* xp_ptr = nullptr;
    cudaGetSymbolAddress(&xp_ptr, g_xp);
    float* xp = (float*)xp_ptr;

    cudaFuncSetAttribute(rnn_scan_kernel,
                         cudaFuncAttributeMaxDynamicSharedMemorySize,
                         SMEM_U32 * (int)sizeof(unsigned));

    // 0) reset flags, seed h0 as fp16 pairs
    rnn_init<<<129, 256>>>(h0);

    // 1) x_proj = inputs @ W_xh + b_h   (tf32 TC)
    gemm_tf32_bias<<<dim3(RH / 128, (RB * RT) / 128), 256>>>(
        RB * RT, RH, RI, inputs, W_xh, b_h, xp);

    // 2) persistent recurrent scan (fp16-pair TC, direct-LDG fragments)
    rnn_scan_kernel<<<128, SCAN_THREADS, SMEM_U32 * sizeof(unsigned)>>>(W_hh, out);

    // 3) outputs = hidden_states @ W_hy + b_y   (tf32 TC)
    gemm_tf32_bias<<<dim3(RO / 128, (RB * RT) / 128), 256>>>(
        RB * RT, RO, RH, xp, W_hy, b_y, out);
}

// round 9
// speedup vs baseline: 2.3315x; 1.0373x over previous
#include <cuda_runtime.h>
#include <cuda_bf16.h>
#include <cuda_fp16.h>
#include <cstdint>
#include <cstddef>

// Problem constants
#define RB 64      // batch
#define RT 512     // time steps
#define RI 512     // input dim
#define RH 1024    // hidden dim
#define RO 512     // output dim
#define NBUF 4     // h ring-buffer depth

// ---------------------------------------------------------------------------
// Scratch (device globals; no allocation allowed)
// ---------------------------------------------------------------------------
__device__ float g_xp[(size_t)RB * RT * RH];   // x_proj, then hidden states (in place)
__device__ uint2 g_hp[NBUF * 512 * 64];        // h fp16 pairs: [buf][k2][b] = {hi_pair, lo_pair}
__device__ unsigned g_wflag[128 * 32];         // per-CTA counting write flags: 4 quadrants at +0,+8,+16,+24
__device__ unsigned g_rflag[128 * 32];         // per-CTA read flags, 128B apart

// ---------------------------------------------------------------------------
// Helpers
// ---------------------------------------------------------------------------
__device__ __forceinline__ unsigned to_tf32(float f) {
    unsigned u;
    asm("cvt.rna.tf32.f32 %0,%1;" : "=r"(u) : "f"(f));
    return u;
}
__device__ __forceinline__ void mma_tf32(float* d,
                                         const unsigned* a, const unsigned* b,
                                         const float* c) {
    asm("mma.sync.aligned.m16n8k8.row.col.f32.tf32.tf32.f32 "
        "{%0,%1,%2,%3},{%4,%5,%6,%7},{%8,%9},{%10,%11,%12,%13};"
        : "=f"(d[0]), "=f"(d[1]), "=f"(d[2]), "=f"(d[3])
        : "r"(a[0]), "r"(a[1]), "r"(a[2]), "r"(a[3]),
          "r"(b[0]), "r"(b[1]),
          "f"(c[0]), "f"(c[1]), "f"(c[2]), "f"(c[3]));
}
// fp16 MMA, fp32 accumulate (hi term)
__device__ __forceinline__ void mma_f16(float* d,
                                        const unsigned* a, unsigned b0, unsigned b1) {
    asm("mma.sync.aligned.m16n8k16.row.col.f32.f16.f16.f32 "
        "{%0,%1,%2,%3},{%4,%5,%6,%7},{%8,%9},{%0,%1,%2,%3};"
        : "+f"(d[0]), "+f"(d[1]), "+f"(d[2]), "+f"(d[3])
        : "r"(a[0]), "r"(a[1]), "r"(a[2]), "r"(a[3]),
          "r"(b0), "r"(b1));
}
// fp16 MMA, fp16 accumulate (lo term — tiny magnitude, rel err negligible)
__device__ __forceinline__ void mma_f16_lo(unsigned* d,
                                           const unsigned* a, unsigned b0, unsigned b1) {
    asm("mma.sync.aligned.m16n8k16.row.col.f16.f16.f16.f16 "
        "{%0,%1},{%2,%3,%4,%5},{%6,%7},{%0,%1};"
        : "+r"(d[0]), "+r"(d[1])
        : "r"(a[0]), "r"(a[1]), "r"(a[2]), "r"(a[3]),
          "r"(b0), "r"(b1));
}
__device__ __forceinline__ void flag_release(unsigned* p, unsigned v) {
    asm volatile("st.release.gpu.global.u32 [%0],%1;" :: "l"(p), "r"(v) : "memory");
}
__device__ __forceinline__ unsigned flag_acquire(const unsigned* p) {
    unsigned v;
    asm volatile("ld.acquire.gpu.global.u32 %0,[%1];" : "=r"(v) : "l"(p) : "memory");
    return v;
}
__device__ __forceinline__ void flag_red_add(unsigned* p) {
    asm volatile("red.release.gpu.global.add.u32 [%0],1;" :: "l"(p) : "memory");
}
// fp16 hi/lo split of an fp32 value (|v| <= ~1, range-safe)
__device__ __forceinline__ void f16_split(float v, unsigned short& hb, unsigned short& lb) {
    __half h = __float2half_rn(v);
    float r = v - __half2float(h);
    __half l = __float2half_rn(r);
    hb = __half_as_ushort(h);
    lb = __half_as_ushort(l);
}
__device__ __forceinline__ uint2 ldcg_u2(const uint2* p) {
    uint2 v;
    asm volatile("ld.global.cg.v2.u32 {%0,%1},[%2];" : "=r"(v.x), "=r"(v.y) : "l"(p));
    return v;
}

// ---------------------------------------------------------------------------
// Init: zero flags, seed g_hp buf0 from initial_hidden [b][j]
// ---------------------------------------------------------------------------
__global__ void rnn_init(const float* __restrict__ h0) {
    int bid = blockIdx.x;
    if (bid < 128) {
        int idx = bid * 256 + threadIdx.x;      // 0..32767 pairs
        int k2 = idx >> 6;                       // 0..511
        int b  = idx & 63;
        float v0 = h0[b * RH + 2 * k2];
        float v1 = h0[b * RH + 2 * k2 + 1];
        unsigned short h0b, l0b, h1b, l1b;
        f16_split(v0, h0b, l0b);
        f16_split(v1, h1b, l1b);
        g_hp[k2 * 64 + b] = make_uint2(
            (unsigned)h0b | ((unsigned)h1b << 16),
            (unsigned)l0b | ((unsigned)l1b << 16));
    } else {
        for (int i = threadIdx.x; i < 128 * 32; i += 256) {
            g_wflag[i] = 0;
            g_rflag[i] = 0;
        }
    }
}

// ---------------------------------------------------------------------------
// TF32 tensor-core GEMM with bias (unchanged — known good 309us each)
// ---------------------------------------------------------------------------
#define ASTR 20
#define BSTR 132
__global__ void __launch_bounds__(256) gemm_tf32_bias(
    int M, int N, int K,
    const float* __restrict__ A, const float* __restrict__ B,
    const float* __restrict__ bias, float* __restrict__ C)
{
    __shared__ unsigned As[128 * ASTR];
    __shared__ unsigned Bs[16 * BSTR];

    const int tid  = threadIdx.x;
    const int lane = tid & 31, wid = tid >> 5;
    const int g  = lane >> 2, tg = lane & 3;
    const int wm = (wid & 3) << 5;
    const int wn = (wid >> 2) << 6;
    const int bx = blockIdx.x << 7, by = blockIdx.y << 7;

    const int ar  = tid >> 2, akq = (tid & 3) << 2;
    const float* Ag = A + (size_t)(by + ar) * K + akq;
    const int bk = tid >> 5, bc = (tid & 31) << 2;
    const float* Bg = B + (size_t)bk * N + bx + bc;

    float4 pa0 = *(const float4*)(Ag);
    float4 pa1 = *(const float4*)(Ag + (size_t)64 * K);
    float4 pb0 = *(const float4*)(Bg);
    float4 pb1 = *(const float4*)(Bg + (size_t)8 * N);

    float acc[2][8][4];
#pragma unroll
    for (int i = 0; i < 2; i++)
#pragma unroll
        for (int j = 0; j < 8; j++)
#pragma unroll
            for (int l = 0; l < 4; l++) acc[i][j][l] = 0.f;

    for (int k0 = 0; ; ) {
        {
            uint4 va0 = make_uint4(to_tf32(pa0.x), to_tf32(pa0.y), to_tf32(pa0.z), to_tf32(pa0.w));
            uint4 va1 = make_uint4(to_tf32(pa1.x), to_tf32(pa1.y), to_tf32(pa1.z), to_tf32(pa1.w));
            *(uint4*)&As[ar * ASTR + akq]        = va0;
            *(uint4*)&As[(ar + 64) * ASTR + akq] = va1;
            uint4 vb0 = make_uint4(to_tf32(pb0.x), to_tf32(pb0.y), to_tf32(pb0.z), to_tf32(pb0.w));
            uint4 vb1 = make_uint4(to_tf32(pb1.x), to_tf32(pb1.y), to_tf32(pb1.z), to_tf32(pb1.w));
            *(uint4*)&Bs[bk * BSTR + bc]       = vb0;
            *(uint4*)&Bs[(bk + 8) * BSTR + bc] = vb1;
        }
        __syncthreads();

        bool more = (k0 + 16) < K;
        if (more) {
            pa0 = *(const float4*)(Ag + k0 + 16);
            pa1 = *(const float4*)(Ag + (size_t)64 * K + k0 + 16);
            pb0 = *(const float4*)(Bg + (size_t)(k0 + 16) * N);
            pb1 = *(const float4*)(Bg + (size_t)(k0 + 24) * N);
        }

#pragma unroll
        for (int ks = 0; ks < 16; ks += 8) {
            unsigned af[2][4], bf[8][2];
#pragma unroll
            for (int mt = 0; mt < 2; mt++) {
                int r = wm + (mt << 4) + g;
                af[mt][0] = As[r * ASTR + ks + tg];
                af[mt][1] = As[(r + 8) * ASTR + ks + tg];
                af[mt][2] = As[r * ASTR + ks + tg + 4];
                af[mt][3] = As[(r + 8) * ASTR + ks + tg + 4];
            }
#pragma unroll
            for (int nt = 0; nt < 8; nt++) {
                int c = wn + (nt << 3) + g;
                bf[nt][0] = Bs[(ks + tg) * BSTR + c];
                bf[nt][1] = Bs[(ks + tg + 4) * BSTR + c];
            }
#pragma unroll
            for (int mt = 0; mt < 2; mt++)
#pragma unroll
                for (int nt = 0; nt < 8; nt++)
                    mma_tf32(acc[mt][nt], af[mt], bf[nt], acc[mt][nt]);
        }
        __syncthreads();

        k0 += 16;
        if (!more) break;
    }

#pragma unroll
    for (int mt = 0; mt < 2; mt++) {
        int r0 = by + wm + (mt << 4) + g;
#pragma unroll
        for (int nt = 0; nt < 8; nt++) {
            int col = bx + wn + (nt << 3) + (tg << 1);
            float b0v = bias[col], b1v = bias[col + 1];
            float2 v0 = make_float2(acc[mt][nt][0] + b0v, acc[mt][nt][1] + b1v);
            float2 v1 = make_float2(acc[mt][nt][2] + b0v, acc[mt][nt][3] + b1v);
            *(float2*)&C[(size_t)r0 * N + col]       = v0;
            *(float2*)&C[(size_t)(r0 + 8) * N + col] = v1;
        }
    }
}

// ---------------------------------------------------------------------------
// Persistent recurrent scan, v8:
//  - hi-term MMAs fp32-acc, lo-term MMAs fp16-acc (rt halves; err ~5e-7)
//  - double-buffered Red -> SINGLE __syncthreads per step
//  - per-warp counting release: red.release.add on 4 quadrant counters
//    (quadrant q collects warps {q,q+4,q+8,q+12}; value 4(t+1) after step t)
//  - consumer poll: lane&7 -> {2 producers} x {4 quadrants}, target 4t
// ---------------------------------------------------------------------------
#define SCAN_THREADS 512
#define SMEM_U32 (16384 + 2 * 16 * 544)

__global__ void __launch_bounds__(SCAN_THREADS) rnn_scan_kernel(
    const float* __restrict__ W_hh, float* __restrict__ out)
{
    extern __shared__ unsigned smu[];
    unsigned* W2   = smu;                     // [k2=512][32j] fp16x2, swizzled (64KB)
    float*    Red0 = (float*)(smu + 16384);   // 16*544 floats
    float*    Red1 = Red0 + 16 * 544;         // second buffer

    const int cta = blockIdx.x;
    const int g   = cta >> 5;            // batch group 0..3
    const int cg  = cta & 31;            // col group 0..31
    const int gb0 = g << 4;
    const int gj0 = cg << 5;
    const int tid = threadIdx.x;
    const int lane = tid & 31;
    const int s    = tid >> 5;           // warp id = k-slice
    const int tg   = lane & 3;
    const int r    = lane >> 2;          // 0..7
    const int k2base = s << 5;

    // one-time: convert W_hh[:, gj0:gj0+32] to fp16 k-pairs in smem (swizzled)
    for (int i = 0; i < 32; ++i) {
        int idx = i * SCAN_THREADS + tid;
        int k2 = idx >> 5, j = idx & 31;
        float w0 = W_hh[(size_t)(2 * k2) * RH + gj0 + j];
        float w1 = W_hh[(size_t)(2 * k2 + 1) * RH + gj0 + j];
        unsigned short a = __half_as_ushort(__float2half_rn(w0));
        unsigned short b = __half_as_ushort(__float2half_rn(w1));
        int dst = k2 * 32 + (j ^ ((k2 & 3) << 3));
        W2[dst] = (unsigned)a | ((unsigned)b << 16);
    }

    // finalize mapping
    const int fb = tid >> 5;             // 0..15 (= warp id)
    const int fj = tid & 31;             // 0..31

    // poll mapping: lane&1 -> producer CTA (2s or 2s+1); (lane>>1)&3 -> quadrant
    const unsigned* prodflag =
        &g_wflag[((g << 5) + (s << 1) + (lane & 1)) * 32 + (((lane >> 1) & 3) << 3)];
    const unsigned* grflag = &g_rflag[((g << 5) + lane) * 32];
    unsigned* my_wflag_q = &g_wflag[cta * 32 + ((s & 3) << 3)];
    unsigned* my_rflag   = &g_rflag[cta * 32];

    __syncthreads();   // W smem ready

    for (int t = 0; t < RT; ++t) {
        const unsigned bsrc = (unsigned)(t & 3) * (512 * 64);
        const unsigned bdst = (unsigned)((t + 1) & 3) * (512 * 64);
        float* RedT = (t & 1) ? Red1 : Red0;

        // x_proj prefetch (independent of flags; streaming hint)
        const size_t xpi = ((size_t)(gb0 + fb) * RT + t) * RH + gj0 + fj;
        const float xpv = __ldcs(&g_xp[xpi]);

        // 1) wait for this warp's 2 producers (each quadrant counter >= 4t)
        if (t > 0) {
            const unsigned tgt = 4u * (unsigned)t;
            while (flag_acquire(prodflag) < tgt) { }
            __syncwarp();
        }
        // warp 15: early-load group read-acks
        unsigned rv = 0;
        if (s == 15) rv = flag_acquire(grflag);

        // 2) direct LDG of all A-fragments (16 x LDG.64, high MLP)
        unsigned ah[4][4], al[4][4];
#pragma unroll
        for (int cc = 0; cc < 4; ++cc) {
            const int k2a = k2base + (cc << 3) + tg;
            uint2 v0 = ldcg_u2(&g_hp[bsrc + k2a * 64 + gb0 + r]);
            uint2 v1 = ldcg_u2(&g_hp[bsrc + k2a * 64 + gb0 + r + 8]);
            uint2 v2 = ldcg_u2(&g_hp[bsrc + (k2a + 4) * 64 + gb0 + r]);
            uint2 v3 = ldcg_u2(&g_hp[bsrc + (k2a + 4) * 64 + gb0 + r + 8]);
            ah[cc][0] = v0.x; al[cc][0] = v0.y;
            ah[cc][1] = v1.x; al[cc][1] = v1.y;
            ah[cc][2] = v2.x; al[cc][2] = v2.y;
            ah[cc][3] = v3.x; al[cc][3] = v3.y;
        }

        // 3) MMA: hi -> fp32 acc (16 MMAs), lo -> fp16 acc (16 MMAs)
        float acc[4][4];
        unsigned dlo[4][2];
#pragma unroll
        for (int nt = 0; nt < 4; nt++) {
#pragma unroll
            for (int l = 0; l < 4; l++) acc[nt][l] = 0.f;
            dlo[nt][0] = 0u; dlo[nt][1] = 0u;
        }

#pragma unroll
        for (int cc = 0; cc < 4; ++cc) {
            const int k2a = k2base + (cc << 3) + tg;
#pragma unroll
            for (int nt = 0; nt < 4; ++nt) {
                const int c0 = ((nt << 3) + r) ^ (tg << 3);
                unsigned b0 = W2[k2a * 32 + c0];
                unsigned b1 = W2[(k2a + 4) * 32 + c0];
                mma_f16(acc[nt], ah[cc], b0, b1);
                mma_f16_lo(dlo[nt], al[cc], b0, b1);
            }
        }

        // 4) fold lo into hi, write partials: RedT[s*544 + j*17 + b]
        {
            float* rp = RedT + s * 544;
#pragma unroll
            for (int nt = 0; nt < 4; ++nt) {
                float2 lo01 = __half22float2(*reinterpret_cast<__half2*>(&dlo[nt][0]));
                float2 lo23 = __half22float2(*reinterpret_cast<__half2*>(&dlo[nt][1]));
                int j0 = (nt << 3) + (tg << 1);
                rp[j0 * 17 + r]            = acc[nt][0] + lo01.x;
                rp[(j0 + 1) * 17 + r]      = acc[nt][1] + lo01.y;
                rp[j0 * 17 + r + 8]        = acc[nt][2] + lo23.x;
                rp[(j0 + 1) * 17 + r + 8]  = acc[nt][3] + lo23.y;
            }
        }
        // 5) warp 15: back-pressure — buf[(t+1)%4] free once rflags >= t-2
        if (s == 15) {
            int tgt = t - 2;
            if (tgt > 0) {
                while (!__all_sync(0xffffffffu, (int)rv >= tgt)) {
                    rv = flag_acquire(grflag);
                }
            }
        }
        __syncthreads();   // the ONLY barrier: Red complete, back-pressure ok, LDGs consumed

        // 6) publish read-ack
        if (tid == 0) flag_release(my_rflag, (unsigned)(t + 1));

        // 7) finalize: reduce 16 partials, tanh, store h FIRST, then release
        {
            float v = 0.f;
            const float* rp = RedT + fj * 17 + fb;
#pragma unroll
            for (int ss = 0; ss < 16; ++ss) v += rp[ss * 544];
            float hv = tanhf(v + xpv);

            unsigned short hb, lb;
            f16_split(hv, hb, lb);
            unsigned both = (unsigned)hb | ((unsigned)lb << 16);
            unsigned nb = __shfl_down_sync(0xffffffffu, both, 1);
            if ((fj & 1) == 0) {
                unsigned hi_pair = (both & 0xffffu) | ((nb & 0xffffu) << 16);
                unsigned lo_pair = (both >> 16) | (nb & 0xffff0000u);
                int k2g = (cg << 4) + (fj >> 1);
                g_hp[bdst + k2g * 64 + gb0 + fb] = make_uint2(hi_pair, lo_pair);
            }
            __syncwarp();
            if (lane == 0) flag_red_add(my_wflag_q);   // warp's h visible -> count++

            __stcs(&g_xp[xpi], hv);                    // hidden-state history (stream)
            if (t == RT - 1)
                out[(size_t)RB * RT * RO + (size_t)(gb0 + fb) * RH + gj0 + fj] = hv;
        }
    }
}

// ---------------------------------------------------------------------------
// Launch
// ---------------------------------------------------------------------------
extern "C" void kernel_launch(void* const* d_in, const int* in_sizes, int n_in,
                              void* d_out, int out_size)
{
    const float* inputs = (const float*)d_in[0];
    const float* h0     = (const float*)d_in[1];
    const float* W_xh   = (const float*)d_in[2];
    const float* W_hh   = (const float*)d_in[3];
    const float* W_hy   = (const float*)d_in[4];
    const float* b_h    = (const float*)d_in[5];
    const float* b_y    = (const float*)d_in[6];
    float* out = (float*)d_out;

    void* xp_ptr = nullptr;
    cudaGetSymbolAddress(&xp_ptr, g_xp);
    float* xp = (float*)xp_ptr;

    cudaFuncSetAttribute(rnn_scan_kernel,
                         cudaFuncAttributeMaxDynamicSharedMemorySize,
                         SMEM_U32 * (int)sizeof(unsigned));

    // 0) reset flags, seed h0 as fp16 pairs
    rnn_init<<<129, 256>>>(h0);

    // 1) x_proj = inputs @ W_xh + b_h   (tf32 TC)
    gemm_tf32_bias<<<dim3(RH / 128, (RB * RT) / 128), 256>>>(
        RB * RT, RH, RI, inputs, W_xh, b_h, xp);

    // 2) persistent recurrent scan
    rnn_scan_kernel<<<128, SCAN_THREADS, SMEM_U32 * sizeof(unsigned)>>>(W_hh, out);

    // 3) outputs = hidden_states @ W_hy + b_y   (tf32 TC)
    gemm_tf32_bias<<<dim3(RO / 128, (RB * RT) / 128), 256>>>(
        RB * RT, RO, RH, xp, W_hy, b_y, out);
}

// round 10
// speedup vs baseline: 2.5634x; 1.0995x over previous
#include <cuda_runtime.h>
#include <cuda_bf16.h>
#include <cuda_fp16.h>
#include <cstdint>
#include <cstddef>

// Problem constants
#define RB 64      // batch
#define RT 512     // time steps
#define RI 512     // input dim
#define RH 1024    // hidden dim
#define RO 512     // output dim
#define NBUF 4     // h ring-buffer depth

// ---------------------------------------------------------------------------
// Scratch (device globals; no allocation allowed)
// ---------------------------------------------------------------------------
__device__ float g_xp[(size_t)RB * RT * RH];   // x_proj, then hidden states (in place)
__device__ uint2 g_hp[NBUF * 512 * 64];        // h fp16 pairs: [buf][k2][b] = {hi_pair, lo_pair}
__device__ unsigned g_wflag[128 * 32];         // per-CTA counting write flags (4 quadrants)
__device__ unsigned g_rflag[128 * 32];         // per-CTA read flags, 128B apart

// ---------------------------------------------------------------------------
// Helpers
// ---------------------------------------------------------------------------
// fp16 MMA, fp32 accumulate
__device__ __forceinline__ void mma_f16(float* d,
                                        const unsigned* a, unsigned b0, unsigned b1) {
    asm("mma.sync.aligned.m16n8k16.row.col.f32.f16.f16.f32 "
        "{%0,%1,%2,%3},{%4,%5,%6,%7},{%8,%9},{%0,%1,%2,%3};"
        : "+f"(d[0]), "+f"(d[1]), "+f"(d[2]), "+f"(d[3])
        : "r"(a[0]), "r"(a[1]), "r"(a[2]), "r"(a[3]),
          "r"(b0), "r"(b1));
}
// fp16 MMA, fp16 accumulate (lo term — tiny magnitude)
__device__ __forceinline__ void mma_f16_lo(unsigned* d,
                                           const unsigned* a, unsigned b0, unsigned b1) {
    asm("mma.sync.aligned.m16n8k16.row.col.f16.f16.f16.f16 "
        "{%0,%1},{%2,%3,%4,%5},{%6,%7},{%0,%1};"
        : "+r"(d[0]), "+r"(d[1])
        : "r"(a[0]), "r"(a[1]), "r"(a[2]), "r"(a[3]),
          "r"(b0), "r"(b1));
}
__device__ __forceinline__ void flag_release(unsigned* p, unsigned v) {
    asm volatile("st.release.gpu.global.u32 [%0],%1;" :: "l"(p), "r"(v) : "memory");
}
__device__ __forceinline__ unsigned flag_acquire(const unsigned* p) {
    unsigned v;
    asm volatile("ld.acquire.gpu.global.u32 %0,[%1];" : "=r"(v) : "l"(p) : "memory");
    return v;
}
__device__ __forceinline__ void flag_red_add(unsigned* p) {
    asm volatile("red.release.gpu.global.add.u32 [%0],1;" :: "l"(p) : "memory");
}
__device__ __forceinline__ void f16_split(float v, unsigned short& hb, unsigned short& lb) {
    __half h = __float2half_rn(v);
    float r = v - __half2float(h);
    __half l = __float2half_rn(r);
    hb = __half_as_ushort(h);
    lb = __half_as_ushort(l);
}
__device__ __forceinline__ uint2 ldcg_u2(const uint2* p) {
    uint2 v;
    asm volatile("ld.global.cg.v2.u32 {%0,%1},[%2];" : "=r"(v.x), "=r"(v.y) : "l"(p));
    return v;
}
__device__ __forceinline__ unsigned h2pack(float a, float b) {
    __half2 h = __floats2half2_rn(a, b);   // low = a, high = b
    return *reinterpret_cast<unsigned*>(&h);
}

// ---------------------------------------------------------------------------
// Init: zero flags, seed g_hp buf0 from initial_hidden [b][j]
// ---------------------------------------------------------------------------
__global__ void rnn_init(const float* __restrict__ h0) {
    int bid = blockIdx.x;
    if (bid < 128) {
        int idx = bid * 256 + threadIdx.x;      // 0..32767 pairs
        int k2 = idx >> 6;                       // 0..511
        int b  = idx & 63;
        float v0 = h0[b * RH + 2 * k2];
        float v1 = h0[b * RH + 2 * k2 + 1];
        unsigned short h0b, l0b, h1b, l1b;
        f16_split(v0, h0b, l0b);
        f16_split(v1, h1b, l1b);
        g_hp[k2 * 64 + b] = make_uint2(
            (unsigned)h0b | ((unsigned)h1b << 16),
            (unsigned)l0b | ((unsigned)l1b << 16));
    } else {
        for (int i = threadIdx.x; i < 128 * 32; i += 256) {
            g_wflag[i] = 0;
            g_rflag[i] = 0;
        }
    }
}

// ---------------------------------------------------------------------------
// FP16 tensor-core GEMM with bias:  C[M,N] = A[M,K] @ B[K,N] + bias[N]
// fp16 inputs (same 10-bit mantissa as tf32; ranges safe here), fp32 accum.
// 128x128x16 tile, 256 thr = 8 warps (4x2), warp tile 32x64.
// As [m=128][k2=8] u32 fp16-pairs, stride 12 (frag loads cover all 32 banks);
// Bs [k2=8][n=128] u32 fp16-pairs (k even low), stride 136 (all 32 banks).
// Half the MMAs and half the LDS bytes of the tf32 version.
// ---------------------------------------------------------------------------
#define ASTR2 12
#define BSTR2 136
__global__ void __launch_bounds__(256) gemm_f16_bias(
    int M, int N, int K,
    const float* __restrict__ A, const float* __restrict__ B,
    const float* __restrict__ bias, float* __restrict__ C)
{
    __shared__ unsigned As[128 * ASTR2];   // 6 KB
    __shared__ unsigned Bs[8 * BSTR2];     // 4.25 KB

    const int tid  = threadIdx.x;
    const int lane = tid & 31, wid = tid >> 5;
    const int g  = lane >> 2, tg = lane & 3;
    const int wm = (wid & 3) << 5;          // warp M offset
    const int wn = (wid >> 2) << 6;         // warp N offset
    const int bx = blockIdx.x << 7, by = blockIdx.y << 7;

    // A loader: row ar, k-half ah (0 or 8)
    const int ar = tid >> 1, ah = (tid & 1) << 3;
    const float* Ag = A + (size_t)(by + ar) * K + ah;
    // B loader: k-pair row bk2 (0..7), col quad bn
    const int bk2 = tid >> 5, bn = (tid & 31) << 2;
    const float* Bg = B + (size_t)(2 * bk2) * N + bx + bn;

    float4 pa0 = *(const float4*)(Ag);
    float4 pa1 = *(const float4*)(Ag + 4);
    float4 pb0 = *(const float4*)(Bg);
    float4 pb1 = *(const float4*)(Bg + (size_t)N);

    float acc[2][8][4];
#pragma unroll
    for (int i = 0; i < 2; i++)
#pragma unroll
        for (int j = 0; j < 8; j++)
#pragma unroll
            for (int l = 0; l < 4; l++) acc[i][j][l] = 0.f;

    for (int k0 = 0; ; ) {
        // pack prefetched fp32 into fp16-pair smem
        {
            uint4 va = make_uint4(h2pack(pa0.x, pa0.y), h2pack(pa0.z, pa0.w),
                                  h2pack(pa1.x, pa1.y), h2pack(pa1.z, pa1.w));
            *(uint4*)&As[ar * ASTR2 + (ah >> 1)] = va;       // k-pairs ah/2 .. ah/2+3
            uint4 vb = make_uint4(h2pack(pb0.x, pb1.x), h2pack(pb0.y, pb1.y),
                                  h2pack(pb0.z, pb1.z), h2pack(pb0.w, pb1.w));
            *(uint4*)&Bs[bk2 * BSTR2 + bn] = vb;             // (k even, k odd) pairs
        }
        __syncthreads();

        bool more = (k0 + 16) < K;
        if (more) {
            pa0 = *(const float4*)(Ag + k0 + 16);
            pa1 = *(const float4*)(Ag + k0 + 20);
            pb0 = *(const float4*)(Bg + (size_t)(k0 + 16) * N);
            pb1 = *(const float4*)(Bg + (size_t)(k0 + 17) * N);
        }

        // fragments + 16 MMAs (k16 per MMA)
        {
            unsigned af[2][4], bf[8][2];
#pragma unroll
            for (int mt = 0; mt < 2; mt++) {
                int row = wm + (mt << 4) + g;
                af[mt][0] = As[row * ASTR2 + tg];
                af[mt][1] = As[(row + 8) * ASTR2 + tg];
                af[mt][2] = As[row * ASTR2 + tg + 4];
                af[mt][3] = As[(row + 8) * ASTR2 + tg + 4];
            }
#pragma unroll
            for (int nt = 0; nt < 8; nt++) {
                int c = wn + (nt << 3) + g;
                bf[nt][0] = Bs[tg * BSTR2 + c];
                bf[nt][1] = Bs[(tg + 4) * BSTR2 + c];
            }
#pragma unroll
            for (int mt = 0; mt < 2; mt++)
#pragma unroll
                for (int nt = 0; nt < 8; nt++)
                    mma_f16(acc[mt][nt], af[mt], bf[nt][0], bf[nt][1]);
        }
        __syncthreads();

        k0 += 16;
        if (!more) break;
    }

    // Epilogue: add bias, store float2 pairs
#pragma unroll
    for (int mt = 0; mt < 2; mt++) {
        int r0 = by + wm + (mt << 4) + g;
#pragma unroll
        for (int nt = 0; nt < 8; nt++) {
            int col = bx + wn + (nt << 3) + (tg << 1);
            float b0v = bias[col], b1v = bias[col + 1];
            float2 v0 = make_float2(acc[mt][nt][0] + b0v, acc[mt][nt][1] + b1v);
            float2 v1 = make_float2(acc[mt][nt][2] + b0v, acc[mt][nt][3] + b1v);
            *(float2*)&C[(size_t)r0 * N + col]       = v0;
            *(float2*)&C[(size_t)(r0 + 8) * N + col] = v1;
        }
    }
}

// ---------------------------------------------------------------------------
// Persistent recurrent scan (unchanged from R9 — proven at ~3.7us/step):
// fp16-pair h x fp16 W, hi fp32-acc + lo fp16-acc, single barrier/step,
// counting quadrant releases, 4-deep ring, read-ack back-pressure.
// ---------------------------------------------------------------------------
#define SCAN_THREADS 512
#define SMEM_U32 (16384 + 2 * 16 * 544)

__global__ void __launch_bounds__(SCAN_THREADS) rnn_scan_kernel(
    const float* __restrict__ W_hh, float* __restrict__ out)
{
    extern __shared__ unsigned smu[];
    unsigned* W2   = smu;                     // [k2=512][32j] fp16x2, swizzled (64KB)
    float*    Red0 = (float*)(smu + 16384);
    float*    Red1 = Red0 + 16 * 544;

    const int cta = blockIdx.x;
    const int g   = cta >> 5;
    const int cg  = cta & 31;
    const int gb0 = g << 4;
    const int gj0 = cg << 5;
    const int tid = threadIdx.x;
    const int lane = tid & 31;
    const int s    = tid >> 5;
    const int tg   = lane & 3;
    const int r    = lane >> 2;
    const int k2base = s << 5;

    for (int i = 0; i < 32; ++i) {
        int idx = i * SCAN_THREADS + tid;
        int k2 = idx >> 5, j = idx & 31;
        float w0 = W_hh[(size_t)(2 * k2) * RH + gj0 + j];
        float w1 = W_hh[(size_t)(2 * k2 + 1) * RH + gj0 + j];
        unsigned short a = __half_as_ushort(__float2half_rn(w0));
        unsigned short b = __half_as_ushort(__float2half_rn(w1));
        int dst = k2 * 32 + (j ^ ((k2 & 3) << 3));
        W2[dst] = (unsigned)a | ((unsigned)b << 16);
    }

    const int fb = tid >> 5;
    const int fj = tid & 31;

    const unsigned* prodflag =
        &g_wflag[((g << 5) + (s << 1) + (lane & 1)) * 32 + (((lane >> 1) & 3) << 3)];
    const unsigned* grflag = &g_rflag[((g << 5) + lane) * 32];
    unsigned* my_wflag_q = &g_wflag[cta * 32 + ((s & 3) << 3)];
    unsigned* my_rflag   = &g_rflag[cta * 32];

    __syncthreads();

    for (int t = 0; t < RT; ++t) {
        const unsigned bsrc = (unsigned)(t & 3) * (512 * 64);
        const unsigned bdst = (unsigned)((t + 1) & 3) * (512 * 64);
        float* RedT = (t & 1) ? Red1 : Red0;

        const size_t xpi = ((size_t)(gb0 + fb) * RT + t) * RH + gj0 + fj;
        const float xpv = __ldcs(&g_xp[xpi]);

        if (t > 0) {
            const unsigned tgt = 4u * (unsigned)t;
            while (flag_acquire(prodflag) < tgt) { }
            __syncwarp();
        }
        unsigned rv = 0;
        if (s == 15) rv = flag_acquire(grflag);

        unsigned ah[4][4], al[4][4];
#pragma unroll
        for (int cc = 0; cc < 4; ++cc) {
            const int k2a = k2base + (cc << 3) + tg;
            uint2 v0 = ldcg_u2(&g_hp[bsrc + k2a * 64 + gb0 + r]);
            uint2 v1 = ldcg_u2(&g_hp[bsrc + k2a * 64 + gb0 + r + 8]);
            uint2 v2 = ldcg_u2(&g_hp[bsrc + (k2a + 4) * 64 + gb0 + r]);
            uint2 v3 = ldcg_u2(&g_hp[bsrc + (k2a + 4) * 64 + gb0 + r + 8]);
            ah[cc][0] = v0.x; al[cc][0] = v0.y;
            ah[cc][1] = v1.x; al[cc][1] = v1.y;
            ah[cc][2] = v2.x; al[cc][2] = v2.y;
            ah[cc][3] = v3.x; al[cc][3] = v3.y;
        }

        float acc[4][4];
        unsigned dlo[4][2];
#pragma unroll
        for (int nt = 0; nt < 4; nt++) {
#pragma unroll
            for (int l = 0; l < 4; l++) acc[nt][l] = 0.f;
            dlo[nt][0] = 0u; dlo[nt][1] = 0u;
        }

#pragma unroll
        for (int cc = 0; cc < 4; ++cc) {
            const int k2a = k2base + (cc << 3) + tg;
#pragma unroll
            for (int nt = 0; nt < 4; ++nt) {
                const int c0 = ((nt << 3) + r) ^ (tg << 3);
                unsigned b0 = W2[k2a * 32 + c0];
                unsigned b1 = W2[(k2a + 4) * 32 + c0];
                mma_f16(acc[nt], ah[cc], b0, b1);
                mma_f16_lo(dlo[nt], al[cc], b0, b1);
            }
        }

        {
            float* rp = RedT + s * 544;
#pragma unroll
            for (int nt = 0; nt < 4; ++nt) {
                float2 lo01 = __half22float2(*reinterpret_cast<__half2*>(&dlo[nt][0]));
                float2 lo23 = __half22float2(*reinterpret_cast<__half2*>(&dlo[nt][1]));
                int j0 = (nt << 3) + (tg << 1);
                rp[j0 * 17 + r]            = acc[nt][0] + lo01.x;
                rp[(j0 + 1) * 17 + r]      = acc[nt][1] + lo01.y;
                rp[j0 * 17 + r + 8]        = acc[nt][2] + lo23.x;
                rp[(j0 + 1) * 17 + r + 8]  = acc[nt][3] + lo23.y;
            }
        }
        if (s == 15) {
            int tgt = t - 2;
            if (tgt > 0) {
                while (!__all_sync(0xffffffffu, (int)rv >= tgt)) {
                    rv = flag_acquire(grflag);
                }
            }
        }
        __syncthreads();

        if (tid == 0) flag_release(my_rflag, (unsigned)(t + 1));

        {
            float v = 0.f;
            const float* rp = RedT + fj * 17 + fb;
#pragma unroll
            for (int ss = 0; ss < 16; ++ss) v += rp[ss * 544];
            float hv = tanhf(v + xpv);

            unsigned short hb, lb;
            f16_split(hv, hb, lb);
            unsigned both = (unsigned)hb | ((unsigned)lb << 16);
            unsigned nb = __shfl_down_sync(0xffffffffu, both, 1);
            if ((fj & 1) == 0) {
                unsigned hi_pair = (both & 0xffffu) | ((nb & 0xffffu) << 16);
                unsigned lo_pair = (both >> 16) | (nb & 0xffff0000u);
                int k2g = (cg << 4) + (fj >> 1);
                g_hp[bdst + k2g * 64 + gb0 + fb] = make_uint2(hi_pair, lo_pair);
            }
            __syncwarp();
            if (lane == 0) flag_red_add(my_wflag_q);

            __stcs(&g_xp[xpi], hv);
            if (t == RT - 1)
                out[(size_t)RB * RT * RO + (size_t)(gb0 + fb) * RH + gj0 + fj] = hv;
        }
    }
}

// ---------------------------------------------------------------------------
// Launch
// ---------------------------------------------------------------------------
extern "C" void kernel_launch(void* const* d_in, const int* in_sizes, int n_in,
                              void* d_out, int out_size)
{
    const float* inputs = (const float*)d_in[0];
    const float* h0     = (const float*)d_in[1];
    const float* W_xh   = (const float*)d_in[2];
    const float* W_hh   = (const float*)d_in[3];
    const float* W_hy   = (const float*)d_in[4];
    const float* b_h    = (const float*)d_in[5];
    const float* b_y    = (const float*)d_in[6];
    float* out = (float*)d_out;

    void* xp_ptr = nullptr;
    cudaGetSymbolAddress(&xp_ptr, g_xp);
    float* xp = (float*)xp_ptr;

    cudaFuncSetAttribute(rnn_scan_kernel,
                         cudaFuncAttributeMaxDynamicSharedMemorySize,
                         SMEM_U32 * (int)sizeof(unsigned));

    // 0) reset flags, seed h0 as fp16 pairs
    rnn_init<<<129, 256>>>(h0);

    // 1) x_proj = inputs @ W_xh + b_h   (fp16 TC)
    gemm_f16_bias<<<dim3(RH / 128, (RB * RT) / 128), 256>>>(
        RB * RT, RH, RI, inputs, W_xh, b_h, xp);

    // 2) persistent recurrent scan
    rnn_scan_kernel<<<128, SCAN_THREADS, SMEM_U32 * sizeof(unsigned)>>>(W_hh, out);

    // 3) outputs = hidden_states @ W_hy + b_y   (fp16 TC)
    gemm_f16_bias<<<dim3(RO / 128, (RB * RT) / 128), 256>>>(
        RB * RT, RO, RH, xp, W_hy, b_y, out);
}

// round 11
// speedup vs baseline: 2.8198x; 1.1000x over previous
#include <cuda_runtime.h>
#include <cuda_bf16.h>
#include <cuda_fp16.h>
#include <cstdint>
#include <cstddef>

// Problem constants
#define RB 64      // batch
#define RT 512     // time steps
#define RI 512     // input dim
#define RH 1024    // hidden dim
#define RO 512     // output dim
#define NBUF 4     // h ring-buffer depth

// ---------------------------------------------------------------------------
// Scratch (device globals; no allocation allowed)
// ---------------------------------------------------------------------------
__device__ __half g_xp[(size_t)RB * RT * RH];  // x_proj (fp16), then hidden states (in place)
__device__ unsigned g_h2[NBUF * 512 * 64];     // h fp16 k-pairs: [buf][k2][b]
__device__ unsigned g_wflag[128 * 32];         // per-CTA counting write flags (4 quadrants)
__device__ unsigned g_rflag[128 * 32];         // per-CTA read flags, 128B apart

// ---------------------------------------------------------------------------
// Helpers
// ---------------------------------------------------------------------------
// fp16 MMA, fp32 accumulate
__device__ __forceinline__ void mma_f16(float* d,
                                        const unsigned* a, unsigned b0, unsigned b1) {
    asm("mma.sync.aligned.m16n8k16.row.col.f32.f16.f16.f32 "
        "{%0,%1,%2,%3},{%4,%5,%6,%7},{%8,%9},{%0,%1,%2,%3};"
        : "+f"(d[0]), "+f"(d[1]), "+f"(d[2]), "+f"(d[3])
        : "r"(a[0]), "r"(a[1]), "r"(a[2]), "r"(a[3]),
          "r"(b0), "r"(b1));
}
__device__ __forceinline__ void flag_release(unsigned* p, unsigned v) {
    asm volatile("st.release.gpu.global.u32 [%0],%1;" :: "l"(p), "r"(v) : "memory");
}
__device__ __forceinline__ unsigned flag_acquire(const unsigned* p) {
    unsigned v;
    asm volatile("ld.acquire.gpu.global.u32 %0,[%1];" : "=r"(v) : "l"(p) : "memory");
    return v;
}
__device__ __forceinline__ void flag_red_add(unsigned* p) {
    asm volatile("red.release.gpu.global.add.u32 [%0],1;" :: "l"(p) : "memory");
}
__device__ __forceinline__ unsigned ldcg_u32(const unsigned* p) {
    unsigned v;
    asm volatile("ld.global.cg.u32 %0,[%1];" : "=r"(v) : "l"(p));
    return v;
}
__device__ __forceinline__ unsigned h2pack(float a, float b) {
    __half2 h = __floats2half2_rn(a, b);   // low = a, high = b
    return *reinterpret_cast<unsigned*>(&h);
}
__device__ __forceinline__ void st_u16_cs(__half* p, unsigned short v) {
    asm volatile("st.global.cs.u16 [%0],%1;" :: "l"(p), "h"(v) : "memory");
}
__device__ __forceinline__ unsigned short ld_u16_cs(const __half* p) {
    unsigned short v;
    asm volatile("ld.global.cs.u16 %0,[%1];" : "=h"(v) : "l"(p));
    return v;
}

// ---------------------------------------------------------------------------
// Init: zero flags, seed g_h2 buf0 from initial_hidden [b][j]
// ---------------------------------------------------------------------------
__global__ void rnn_init(const float* __restrict__ h0) {
    int bid = blockIdx.x;
    if (bid < 128) {
        int idx = bid * 256 + threadIdx.x;      // 0..32767 pairs
        int k2 = idx >> 6;                       // 0..511
        int b  = idx & 63;
        float v0 = h0[b * RH + 2 * k2];
        float v1 = h0[b * RH + 2 * k2 + 1];
        g_h2[k2 * 64 + b] = h2pack(v0, v1);
    } else {
        for (int i = threadIdx.x; i < 128 * 32; i += 256) {
            g_wflag[i] = 0;
            g_rflag[i] = 0;
        }
    }
}

// ---------------------------------------------------------------------------
// FP16 tensor-core GEMM, fp32 A input, fp16 OUTPUT:
//   C[M,N] (fp16) = A[M,K](fp32) @ B[K,N](fp32) + bias[N]
// 128x128x16 tile, 256 thr = 8 warps (4x2), warp tile 32x64.
// ---------------------------------------------------------------------------
#define ASTR2 12
#define BSTR2 136
__global__ void __launch_bounds__(256) gemm_f16_bias_h16out(
    int M, int N, int K,
    const float* __restrict__ A, const float* __restrict__ B,
    const float* __restrict__ bias, __half* __restrict__ C)
{
    __shared__ unsigned As[128 * ASTR2];
    __shared__ unsigned Bs[8 * BSTR2];

    const int tid  = threadIdx.x;
    const int lane = tid & 31, wid = tid >> 5;
    const int g  = lane >> 2, tg = lane & 3;
    const int wm = (wid & 3) << 5;
    const int wn = (wid >> 2) << 6;
    const int bx = blockIdx.x << 7, by = blockIdx.y << 7;

    const int ar = tid >> 1, ah = (tid & 1) << 3;
    const float* Ag = A + (size_t)(by + ar) * K + ah;
    const int bk2 = tid >> 5, bn = (tid & 31) << 2;
    const float* Bg = B + (size_t)(2 * bk2) * N + bx + bn;

    float4 pa0 = *(const float4*)(Ag);
    float4 pa1 = *(const float4*)(Ag + 4);
    float4 pb0 = *(const float4*)(Bg);
    float4 pb1 = *(const float4*)(Bg + (size_t)N);

    float acc[2][8][4];
#pragma unroll
    for (int i = 0; i < 2; i++)
#pragma unroll
        for (int j = 0; j < 8; j++)
#pragma unroll
            for (int l = 0; l < 4; l++) acc[i][j][l] = 0.f;

    for (int k0 = 0; ; ) {
        {
            uint4 va = make_uint4(h2pack(pa0.x, pa0.y), h2pack(pa0.z, pa0.w),
                                  h2pack(pa1.x, pa1.y), h2pack(pa1.z, pa1.w));
            *(uint4*)&As[ar * ASTR2 + (ah >> 1)] = va;
            uint4 vb = make_uint4(h2pack(pb0.x, pb1.x), h2pack(pb0.y, pb1.y),
                                  h2pack(pb0.z, pb1.z), h2pack(pb0.w, pb1.w));
            *(uint4*)&Bs[bk2 * BSTR2 + bn] = vb;
        }
        __syncthreads();

        bool more = (k0 + 16) < K;
        if (more) {
            pa0 = *(const float4*)(Ag + k0 + 16);
            pa1 = *(const float4*)(Ag + k0 + 20);
            pb0 = *(const float4*)(Bg + (size_t)(k0 + 16) * N);
            pb1 = *(const float4*)(Bg + (size_t)(k0 + 17) * N);
        }

        {
            unsigned af[2][4], bf[8][2];
#pragma unroll
            for (int mt = 0; mt < 2; mt++) {
                int row = wm + (mt << 4) + g;
                af[mt][0] = As[row * ASTR2 + tg];
                af[mt][1] = As[(row + 8) * ASTR2 + tg];
                af[mt][2] = As[row * ASTR2 + tg + 4];
                af[mt][3] = As[(row + 8) * ASTR2 + tg + 4];
            }
#pragma unroll
            for (int nt = 0; nt < 8; nt++) {
                int c = wn + (nt << 3) + g;
                bf[nt][0] = Bs[tg * BSTR2 + c];
                bf[nt][1] = Bs[(tg + 4) * BSTR2 + c];
            }
#pragma unroll
            for (int mt = 0; mt < 2; mt++)
#pragma unroll
                for (int nt = 0; nt < 8; nt++)
                    mma_f16(acc[mt][nt], af[mt], bf[nt][0], bf[nt][1]);
        }
        __syncthreads();

        k0 += 16;
        if (!more) break;
    }

#pragma unroll
    for (int mt = 0; mt < 2; mt++) {
        int r0 = by + wm + (mt << 4) + g;
#pragma unroll
        for (int nt = 0; nt < 8; nt++) {
            int col = bx + wn + (nt << 3) + (tg << 1);
            float b0v = bias[col], b1v = bias[col + 1];
            *(unsigned*)&C[(size_t)r0 * N + col] =
                h2pack(acc[mt][nt][0] + b0v, acc[mt][nt][1] + b1v);
            *(unsigned*)&C[(size_t)(r0 + 8) * N + col] =
                h2pack(acc[mt][nt][2] + b0v, acc[mt][nt][3] + b1v);
        }
    }
}

// ---------------------------------------------------------------------------
// FP16 tensor-core GEMM, fp16 A input, fp32 output:
//   C[M,N] (fp32) = A[M,K](fp16) @ B[K,N](fp32) + bias[N]
// ---------------------------------------------------------------------------
__global__ void __launch_bounds__(256) gemm_f16A_bias(
    int M, int N, int K,
    const __half* __restrict__ A, const float* __restrict__ B,
    const float* __restrict__ bias, float* __restrict__ C)
{
    __shared__ unsigned As[128 * ASTR2];
    __shared__ unsigned Bs[8 * BSTR2];

    const int tid  = threadIdx.x;
    const int lane = tid & 31, wid = tid >> 5;
    const int g  = lane >> 2, tg = lane & 3;
    const int wm = (wid & 3) << 5;
    const int wn = (wid >> 2) << 6;
    const int bx = blockIdx.x << 7, by = blockIdx.y << 7;

    const int ar = tid >> 1, ah = (tid & 1) << 3;
    const __half* Ag = A + (size_t)(by + ar) * K + ah;
    const int bk2 = tid >> 5, bn = (tid & 31) << 2;
    const float* Bg = B + (size_t)(2 * bk2) * N + bx + bn;

    uint4  pa  = *(const uint4*)(Ag);          // 8 halves = 4 k-pairs
    float4 pb0 = *(const float4*)(Bg);
    float4 pb1 = *(const float4*)(Bg + (size_t)N);

    float acc[2][8][4];
#pragma unroll
    for (int i = 0; i < 2; i++)
#pragma unroll
        for (int j = 0; j < 8; j++)
#pragma unroll
            for (int l = 0; l < 4; l++) acc[i][j][l] = 0.f;

    for (int k0 = 0; ; ) {
        {
            *(uint4*)&As[ar * ASTR2 + (ah >> 1)] = pa;
            uint4 vb = make_uint4(h2pack(pb0.x, pb1.x), h2pack(pb0.y, pb1.y),
                                  h2pack(pb0.z, pb1.z), h2pack(pb0.w, pb1.w));
            *(uint4*)&Bs[bk2 * BSTR2 + bn] = vb;
        }
        __syncthreads();

        bool more = (k0 + 16) < K;
        if (more) {
            pa  = *(const uint4*)(Ag + k0 + 16);
            pb0 = *(const float4*)(Bg + (size_t)(k0 + 16) * N);
            pb1 = *(const float4*)(Bg + (size_t)(k0 + 17) * N);
        }

        {
            unsigned af[2][4], bf[8][2];
#pragma unroll
            for (int mt = 0; mt < 2; mt++) {
                int row = wm + (mt << 4) + g;
                af[mt][0] = As[row * ASTR2 + tg];
                af[mt][1] = As[(row + 8) * ASTR2 + tg];
                af[mt][2] = As[row * ASTR2 + tg + 4];
                af[mt][3] = As[(row + 8) * ASTR2 + tg + 4];
            }
#pragma unroll
            for (int nt = 0; nt < 8; nt++) {
                int c = wn + (nt << 3) + g;
                bf[nt][0] = Bs[tg * BSTR2 + c];
                bf[nt][1] = Bs[(tg + 4) * BSTR2 + c];
            }
#pragma unroll
            for (int mt = 0; mt < 2; mt++)
#pragma unroll
                for (int nt = 0; nt < 8; nt++)
                    mma_f16(acc[mt][nt], af[mt], bf[nt][0], bf[nt][1]);
        }
        __syncthreads();

        k0 += 16;
        if (!more) break;
    }

#pragma unroll
    for (int mt = 0; mt < 2; mt++) {
        int r0 = by + wm + (mt << 4) + g;
#pragma unroll
        for (int nt = 0; nt < 8; nt++) {
            int col = bx + wn + (nt << 3) + (tg << 1);
            float b0v = bias[col], b1v = bias[col + 1];
            float2 v0 = make_float2(acc[mt][nt][0] + b0v, acc[mt][nt][1] + b1v);
            float2 v1 = make_float2(acc[mt][nt][2] + b0v, acc[mt][nt][3] + b1v);
            *(float2*)&C[(size_t)r0 * N + col]       = v0;
            *(float2*)&C[(size_t)(r0 + 8) * N + col] = v1;
        }
    }
}

// ---------------------------------------------------------------------------
// Persistent recurrent scan, v9: single-fp16 h (lo stream dropped — output
// error is W-quantization-dominated, measured). 16 MMAs/warp f32-acc,
// 16 LDG.32 A-fragments, halved h L2 traffic, 8-lane flag polls.
// Flag protocol identical to R8-R10 (proven).
// ---------------------------------------------------------------------------
#define SCAN_THREADS 512
#define SMEM_U32 (16384 + 2 * 16 * 544)

__global__ void __launch_bounds__(SCAN_THREADS) rnn_scan_kernel(
    const float* __restrict__ W_hh, float* __restrict__ out)
{
    extern __shared__ unsigned smu[];
    unsigned* W2   = smu;                     // [k2=512][32j] fp16x2, swizzled (64KB)
    float*    Red0 = (float*)(smu + 16384);
    float*    Red1 = Red0 + 16 * 544;

    const int cta = blockIdx.x;
    const int g   = cta >> 5;
    const int cg  = cta & 31;
    const int gb0 = g << 4;
    const int gj0 = cg << 5;
    const int tid = threadIdx.x;
    const int lane = tid & 31;
    const int s    = tid >> 5;
    const int tg   = lane & 3;
    const int r    = lane >> 2;
    const int k2base = s << 5;

    // one-time: W_hh[:, gj0:gj0+32] -> fp16 k-pairs, swizzled
    for (int i = 0; i < 32; ++i) {
        int idx = i * SCAN_THREADS + tid;
        int k2 = idx >> 5, j = idx & 31;
        float w0 = W_hh[(size_t)(2 * k2) * RH + gj0 + j];
        float w1 = W_hh[(size_t)(2 * k2 + 1) * RH + gj0 + j];
        int dst = k2 * 32 + (j ^ ((k2 & 3) << 3));
        W2[dst] = h2pack(w0, w1);
    }

    const int fb = tid >> 5;
    const int fj = tid & 31;

    const unsigned* prodflag =
        &g_wflag[((g << 5) + (s << 1) + (lane & 1)) * 32 + (((lane >> 1) & 3) << 3)];
    const unsigned* grflag = &g_rflag[((g << 5) + lane) * 32];
    unsigned* my_wflag_q = &g_wflag[cta * 32 + ((s & 3) << 3)];
    unsigned* my_rflag   = &g_rflag[cta * 32];

    __syncthreads();

    for (int t = 0; t < RT; ++t) {
        const unsigned bsrc = (unsigned)(t & 3) * (512 * 64);
        const unsigned bdst = (unsigned)((t + 1) & 3) * (512 * 64);
        float* RedT = (t & 1) ? Red1 : Red0;

        const size_t xpi = ((size_t)(gb0 + fb) * RT + t) * RH + gj0 + fj;
        const float xpv = __half2float(__ushort_as_half(ld_u16_cs(&g_xp[xpi])));

        // 1) wait for this warp's 2 producers (8 distinct flags, lanes 0-7)
        if (t > 0) {
            const unsigned tgt = 4u * (unsigned)t;
            if (lane < 8) {
                while (flag_acquire(prodflag) < tgt) { }
            }
            __syncwarp();
        }
        unsigned rv = 0;
        if (s == 15) rv = flag_acquire(grflag);

        // 2) direct LDG of A-fragments (16 x LDG.32)
        unsigned ah[4][4];
#pragma unroll
        for (int cc = 0; cc < 4; ++cc) {
            const int k2a = k2base + (cc << 3) + tg;
            ah[cc][0] = ldcg_u32(&g_h2[bsrc + k2a * 64 + gb0 + r]);
            ah[cc][1] = ldcg_u32(&g_h2[bsrc + k2a * 64 + gb0 + r + 8]);
            ah[cc][2] = ldcg_u32(&g_h2[bsrc + (k2a + 4) * 64 + gb0 + r]);
            ah[cc][3] = ldcg_u32(&g_h2[bsrc + (k2a + 4) * 64 + gb0 + r + 8]);
        }

        // 3) 16 MMAs, fp32 accum
        float acc[4][4];
#pragma unroll
        for (int nt = 0; nt < 4; nt++)
#pragma unroll
            for (int l = 0; l < 4; l++) acc[nt][l] = 0.f;

#pragma unroll
        for (int cc = 0; cc < 4; ++cc) {
            const int k2a = k2base + (cc << 3) + tg;
#pragma unroll
            for (int nt = 0; nt < 4; ++nt) {
                const int c0 = ((nt << 3) + r) ^ (tg << 3);
                mma_f16(acc[nt], ah[cc], W2[k2a * 32 + c0], W2[(k2a + 4) * 32 + c0]);
            }
        }

        // 4) write partials: RedT[s*544 + j*17 + b]
        {
            float* rp = RedT + s * 544;
#pragma unroll
            for (int nt = 0; nt < 4; ++nt) {
                int j0 = (nt << 3) + (tg << 1);
                rp[j0 * 17 + r]            = acc[nt][0];
                rp[(j0 + 1) * 17 + r]      = acc[nt][1];
                rp[j0 * 17 + r + 8]        = acc[nt][2];
                rp[(j0 + 1) * 17 + r + 8]  = acc[nt][3];
            }
        }
        // 5) warp 15: back-pressure
        if (s == 15) {
            int tgt = t - 2;
            if (tgt > 0) {
                while (!__all_sync(0xffffffffu, (int)rv >= tgt)) {
                    rv = flag_acquire(grflag);
                }
            }
        }
        __syncthreads();

        if (tid == 0) flag_release(my_rflag, (unsigned)(t + 1));

        // 7) finalize: reduce 16 partials, tanh, store h, release
        {
            float v = 0.f;
            const float* rp = RedT + fj * 17 + fb;
#pragma unroll
            for (int ss = 0; ss < 16; ++ss) v += rp[ss * 544];
            float hv = tanhf(v + xpv);

            unsigned short hb = __half_as_ushort(__float2half_rn(hv));
            unsigned nb = __shfl_down_sync(0xffffffffu, (unsigned)hb, 1);
            if ((fj & 1) == 0) {
                int k2g = (cg << 4) + (fj >> 1);
                g_h2[bdst + k2g * 64 + gb0 + fb] =
                    (unsigned)hb | ((nb & 0xffffu) << 16);
            }
            __syncwarp();
            if (lane == 0) flag_red_add(my_wflag_q);

            st_u16_cs(&g_xp[xpi], hb);   // fp16 hidden-state history (GEMM3 input)
            if (t == RT - 1)
                out[(size_t)RB * RT * RO + (size_t)(gb0 + fb) * RH + gj0 + fj] = hv;
        }
    }
}

// ---------------------------------------------------------------------------
// Launch
// ---------------------------------------------------------------------------
extern "C" void kernel_launch(void* const* d_in, const int* in_sizes, int n_in,
                              void* d_out, int out_size)
{
    const float* inputs = (const float*)d_in[0];
    const float* h0     = (const float*)d_in[1];
    const float* W_xh   = (const float*)d_in[2];
    const float* W_hh   = (const float*)d_in[3];
    const float* W_hy   = (const float*)d_in[4];
    const float* b_h    = (const float*)d_in[5];
    const float* b_y    = (const float*)d_in[6];
    float* out = (float*)d_out;

    void* xp_ptr = nullptr;
    cudaGetSymbolAddress(&xp_ptr, g_xp);
    __half* xp = (__half*)xp_ptr;

    cudaFuncSetAttribute(rnn_scan_kernel,
                         cudaFuncAttributeMaxDynamicSharedMemorySize,
                         SMEM_U32 * (int)sizeof(unsigned));

    // 0) reset flags, seed h0 as fp16 pairs
    rnn_init<<<129, 256>>>(h0);

    // 1) x_proj = inputs @ W_xh + b_h   (fp16 TC, fp16 out)
    gemm_f16_bias_h16out<<<dim3(RH / 128, (RB * RT) / 128), 256>>>(
        RB * RT, RH, RI, inputs, W_xh, b_h, xp);

    // 2) persistent recurrent scan
    rnn_scan_kernel<<<128, SCAN_THREADS, SMEM_U32 * sizeof(unsigned)>>>(W_hh, out);

    // 3) outputs = hidden_states(fp16) @ W_hy + b_y   (fp16 TC)
    gemm_f16A_bias<<<dim3(RO / 128, (RB * RT) / 128), 256>>>(
        RB * RT, RO, RH, xp, W_hy, b_y, out);
}